// round 1
// baseline (speedup 1.0000x reference)
#include <cuda_runtime.h>
#include <cstdint>

// ---------------- problem constants ----------------
#define H_HEADS 16
#define DK      64
#define DMODEL  1024
#define BATCH   4
#define SEQ     2048

// ---------------- scratch (static device globals; no allocs) ----------------
__device__ float g_q[(size_t)BATCH * H_HEADS * SEQ * DK];   // (B,H,S,dk)
__device__ float g_k[(size_t)BATCH * H_HEADS * SEQ * DK];
__device__ float g_v[(size_t)BATCH * H_HEADS * SEQ * DK];
__device__ float g_ctx[(size_t)BATCH * SEQ * DMODEL];       // (B,S,H*dk)

// ============================================================================
// SGEMM-NT:  C[m,n] = sum_k A[m,k] * W[n,k] + bias[n]
//   A: M x K row-major, W: N x K row-major (torch Linear weight)
//   mode 0: write to head-split layout (B,H,S,dk)
//   mode 1: plain row-major M x N
// Tiles: BM=BN=128, BK=16, 256 threads, 8x8 per thread (4+4 split strided by 64)
// ============================================================================
#define GBM 128
#define GBN 128
#define GBK 16

__global__ __launch_bounds__(256)
void gemm_nt_kernel(const float* __restrict__ A,
                    const float* __restrict__ W,
                    const float* __restrict__ bias,
                    float* __restrict__ C,
                    int M, int K, int mode)
{
    __shared__ float As[GBK][GBM];
    __shared__ float Bs[GBK][GBN];

    const int tid = threadIdx.x;
    const int tr  = tid >> 4;     // 0..15
    const int tc  = tid & 15;     // 0..15

    const int rowBase = blockIdx.y * GBM;
    const int colBase = blockIdx.x * GBN;

    const float* Aptr = A + (size_t)rowBase * K;
    const float* Wptr = W + (size_t)colBase * K;

    float acc[8][8];
#pragma unroll
    for (int i = 0; i < 8; i++)
#pragma unroll
        for (int j = 0; j < 8; j++) acc[i][j] = 0.f;

    for (int k0 = 0; k0 < K; k0 += GBK) {
        // cooperative load: 128x16 tiles of A and W, stored transposed [k][m]
#pragma unroll
        for (int it = 0; it < 2; it++) {
            int id = tid + 256 * it;          // 0..511
            int r  = id >> 2;                 // 0..127
            int c4 = (id & 3) << 2;           // 0,4,8,12
            float4 fa = *(const float4*)(Aptr + (size_t)r * K + k0 + c4);
            As[c4 + 0][r] = fa.x; As[c4 + 1][r] = fa.y;
            As[c4 + 2][r] = fa.z; As[c4 + 3][r] = fa.w;
            float4 fb = *(const float4*)(Wptr + (size_t)r * K + k0 + c4);
            Bs[c4 + 0][r] = fb.x; Bs[c4 + 1][r] = fb.y;
            Bs[c4 + 2][r] = fb.z; Bs[c4 + 3][r] = fb.w;
        }
        __syncthreads();

#pragma unroll
        for (int kk = 0; kk < GBK; kk++) {
            float a[8], b[8];
            *(float4*)&a[0] = *(const float4*)&As[kk][tr * 4];
            *(float4*)&a[4] = *(const float4*)&As[kk][tr * 4 + 64];
            *(float4*)&b[0] = *(const float4*)&Bs[kk][tc * 4];
            *(float4*)&b[4] = *(const float4*)&Bs[kk][tc * 4 + 64];
#pragma unroll
            for (int i = 0; i < 8; i++)
#pragma unroll
                for (int j = 0; j < 8; j++)
                    acc[i][j] += a[i] * b[j];
        }
        __syncthreads();
    }

    // epilogue
#pragma unroll
    for (int i = 0; i < 8; i++) {
        int rloc = (i < 4) ? (tr * 4 + i) : (64 + tr * 4 + (i - 4));
        int m = rowBase + rloc;
#pragma unroll
        for (int jj = 0; jj < 2; jj++) {
            int n = colBase + tc * 4 + jj * 64;
            float4 v;
            v.x = acc[i][jj * 4 + 0] + bias[n + 0];
            v.y = acc[i][jj * 4 + 1] + bias[n + 1];
            v.z = acc[i][jj * 4 + 2] + bias[n + 2];
            v.w = acc[i][jj * 4 + 3] + bias[n + 3];
            if (mode == 0) {
                int b = m / SEQ, s = m % SEQ;
                int h = n >> 6, d = n & 63;
                *(float4*)(C + ((((size_t)b * H_HEADS + h) * SEQ + s) << 6) + d) = v;
            } else {
                *(float4*)(C + (size_t)m * DMODEL + n) = v;
            }
        }
    }
}

// ============================================================================
// Flash attention (fp32):  per block: one (b,h), 64 queries.
//   Q,K,V: (B,H,S,64).  mask: (B,S) int32 (broadcast over q).
//   ctx out: (B,S,H,64)
// 256 threads = 16x16; score gemm 64x64x64 then online softmax then PV gemm.
// Smem rows padded to 68 floats.
// ============================================================================
#define AW 68
#define ATT_SMEM (4 * 64 * AW * (int)sizeof(float))   // 69632 B

__global__ __launch_bounds__(256)
void attn_kernel(const float* __restrict__ Q,
                 const float* __restrict__ Kg_,
                 const float* __restrict__ Vg_,
                 const int*   __restrict__ mask,
                 float* __restrict__ ctx)
{
    extern __shared__ float sm[];
    float* Qs = sm;                 // [64][AW]  (d-major: Qs[d][q])
    float* Ks = sm + 64 * AW;       // [64][AW]  (d-major: Ks[d][k])
    float* Vs = sm + 2 * 64 * AW;   // [64][AW]  (k-major: Vs[k][d])
    float* Ps = sm + 3 * 64 * AW;   // [64][AW]  (k-major: Ps[k][q])

    const int tid = threadIdx.x;
    const int ty  = tid >> 4;   // 0..15  -> query rows ty*4..+3
    const int tx  = tid & 15;   // 0..15  -> key/dim cols tx*4..+3
    const int qt  = blockIdx.x;
    const int h   = blockIdx.y;
    const int b   = blockIdx.z;

    const size_t bh = (size_t)b * H_HEADS + h;
    const float* Qg = Q   + (bh * SEQ + (size_t)qt * 64) * 64;
    const float* Kg = Kg_ + bh * SEQ * 64;
    const float* Vg = Vg_ + bh * SEQ * 64;
    const int*   mg = mask + (size_t)b * SEQ;

    // load Q transposed into Qs[d][q]
    {
        int q  = tid >> 2;            // 0..63
        int dg = (tid & 3) * 16;      // 0,16,32,48
#pragma unroll
        for (int i = 0; i < 4; i++) {
            int d = dg + i * 4;
            float4 f = *(const float4*)(Qg + (size_t)q * 64 + d);
            Qs[(d + 0) * AW + q] = f.x; Qs[(d + 1) * AW + q] = f.y;
            Qs[(d + 2) * AW + q] = f.z; Qs[(d + 3) * AW + q] = f.w;
        }
    }

    float m_prev[4], l[4], o[4][4];
#pragma unroll
    for (int i = 0; i < 4; i++) {
        m_prev[i] = -1e30f; l[i] = 0.f;
#pragma unroll
        for (int j = 0; j < 4; j++) o[i][j] = 0.f;
    }

    const int nkt = SEQ / 64;
    for (int kt = 0; kt < nkt; kt++) {
        __syncthreads();   // previous-iter smem readers done
        // load K (transposed -> Ks[d][k]) and V (natural -> Vs[k][d])
        {
            int r  = tid >> 2;
            int dg = (tid & 3) * 16;
            const float* kr = Kg + ((size_t)kt * 64 + r) * 64;
            const float* vr = Vg + ((size_t)kt * 64 + r) * 64;
#pragma unroll
            for (int i = 0; i < 4; i++) {
                int d = dg + i * 4;
                float4 f = *(const float4*)(kr + d);
                Ks[(d + 0) * AW + r] = f.x; Ks[(d + 1) * AW + r] = f.y;
                Ks[(d + 2) * AW + r] = f.z; Ks[(d + 3) * AW + r] = f.w;
                float4 g = *(const float4*)(vr + d);
                *(float4*)&Vs[r * AW + d] = g;
            }
        }
        __syncthreads();

        // scores = Q . K^T
        float sacc[4][4];
#pragma unroll
        for (int i = 0; i < 4; i++)
#pragma unroll
            for (int j = 0; j < 4; j++) sacc[i][j] = 0.f;

#pragma unroll 16
        for (int kk = 0; kk < 64; kk++) {
            float4 a4 = *(const float4*)&Qs[kk * AW + ty * 4];
            float4 b4 = *(const float4*)&Ks[kk * AW + tx * 4];
            float a[4] = {a4.x, a4.y, a4.z, a4.w};
            float bb[4] = {b4.x, b4.y, b4.z, b4.w};
#pragma unroll
            for (int i = 0; i < 4; i++)
#pragma unroll
                for (int j = 0; j < 4; j++)
                    sacc[i][j] += a[i] * bb[j];
        }

        // scale + mask
        const int kbase = kt * 64 + tx * 4;
        float sv[4][4];
#pragma unroll
        for (int j = 0; j < 4; j++) {
            int mk = mg[kbase + j];
#pragma unroll
            for (int i = 0; i < 4; i++)
                sv[i][j] = mk ? sacc[i][j] * 0.125f : -1e9f;
        }

        // online softmax (row stats across the 16 tx lanes)
        float p[4][4];
#pragma unroll
        for (int i = 0; i < 4; i++) {
            float rmax = fmaxf(fmaxf(sv[i][0], sv[i][1]), fmaxf(sv[i][2], sv[i][3]));
#pragma unroll
            for (int off = 1; off < 16; off <<= 1)
                rmax = fmaxf(rmax, __shfl_xor_sync(0xffffffffu, rmax, off));
            float mnew = fmaxf(m_prev[i], rmax);
            float fac  = __expf(m_prev[i] - mnew);
            float rsum = 0.f;
#pragma unroll
            for (int j = 0; j < 4; j++) {
                p[i][j] = __expf(sv[i][j] - mnew);
                rsum += p[i][j];
            }
#pragma unroll
            for (int off = 1; off < 16; off <<= 1)
                rsum += __shfl_xor_sync(0xffffffffu, rsum, off);
            l[i] = l[i] * fac + rsum;
            m_prev[i] = mnew;
#pragma unroll
            for (int j = 0; j < 4; j++) o[i][j] *= fac;
        }

        // stage P transposed: Ps[k][q]
#pragma unroll
        for (int j = 0; j < 4; j++)
#pragma unroll
            for (int i = 0; i < 4; i++)
                Ps[(tx * 4 + j) * AW + ty * 4 + i] = p[i][j];
        __syncthreads();

        // O += P . V
#pragma unroll 16
        for (int kk = 0; kk < 64; kk++) {
            float4 p4 = *(const float4*)&Ps[kk * AW + ty * 4];
            float4 v4 = *(const float4*)&Vs[kk * AW + tx * 4];
            float pp[4] = {p4.x, p4.y, p4.z, p4.w};
            float vv[4] = {v4.x, v4.y, v4.z, v4.w};
#pragma unroll
            for (int i = 0; i < 4; i++)
#pragma unroll
                for (int j = 0; j < 4; j++)
                    o[i][j] += pp[i] * vv[j];
        }
    }

    // finalize and write ctx (B,S,H,64)
#pragma unroll
    for (int i = 0; i < 4; i++) {
        int q = qt * 64 + ty * 4 + i;
        float inv = (l[i] > 0.f) ? (1.f / l[i]) : 0.f;
        float4 v;
        v.x = o[i][0] * inv; v.y = o[i][1] * inv;
        v.z = o[i][2] * inv; v.w = o[i][3] * inv;
        *(float4*)(ctx + ((size_t)(b * SEQ + q) * H_HEADS + h) * 64 + tx * 4) = v;
    }
}

// ============================================================================
// launch
// ============================================================================
extern "C" void kernel_launch(void* const* d_in, const int* in_sizes, int n_in,
                              void* d_out, int out_size)
{
    const float* query = (const float*)d_in[0];
    const float* key_  = (const float*)d_in[1];
    const float* value = (const float*)d_in[2];
    const int*   mask  = (const int*)  d_in[3];
    const float* Wq = (const float*)d_in[4];
    const float* bq = (const float*)d_in[5];
    const float* Wk = (const float*)d_in[6];
    const float* bk = (const float*)d_in[7];
    const float* Wv = (const float*)d_in[8];
    const float* bv = (const float*)d_in[9];
    const float* Wo = (const float*)d_in[10];
    const float* bo = (const float*)d_in[11];
    float* out = (float*)d_out;

    float *gq, *gk, *gv, *gctx;
    cudaGetSymbolAddress((void**)&gq,  g_q);
    cudaGetSymbolAddress((void**)&gk,  g_k);
    cudaGetSymbolAddress((void**)&gv,  g_v);
    cudaGetSymbolAddress((void**)&gctx, g_ctx);

    cudaFuncSetAttribute(attn_kernel,
                         cudaFuncAttributeMaxDynamicSharedMemorySize, ATT_SMEM);

    const int M = BATCH * SEQ;                 // 8192
    dim3 ggrid(DMODEL / GBN, M / GBM);         // (8, 64)
    dim3 gblock(256);

    // QKV projections -> head-split layout
    gemm_nt_kernel<<<ggrid, gblock>>>(query, Wq, bq, gq, M, DMODEL, 0);
    gemm_nt_kernel<<<ggrid, gblock>>>(key_,  Wk, bk, gk, M, DMODEL, 0);
    gemm_nt_kernel<<<ggrid, gblock>>>(value, Wv, bv, gv, M, DMODEL, 0);

    // attention
    dim3 agrid(SEQ / 64, H_HEADS, BATCH);      // (32, 16, 4)
    attn_kernel<<<agrid, dim3(256), ATT_SMEM>>>(gq, gk, gv, mask, gctx);

    // output projection -> plain row-major
    gemm_nt_kernel<<<ggrid, gblock>>>(gctx, Wo, bo, out, M, DMODEL, 1);
}

// round 3
// speedup vs baseline: 3.0136x; 3.0136x over previous
#include <cuda_runtime.h>
#include <cstdint>

// ---------------- problem constants ----------------
#define H_HEADS 16
#define DMODEL  1024
#define BATCH   4
#define SEQ     2048

// ---------------- scratch (static device globals; no allocs) ----------------
__device__ float g_q[(size_t)BATCH * H_HEADS * SEQ * 64];   // (B,H,S,dk)
__device__ float g_k[(size_t)BATCH * H_HEADS * SEQ * 64];
__device__ float g_v[(size_t)BATCH * H_HEADS * SEQ * 64];
__device__ float g_ctx[(size_t)BATCH * SEQ * DMODEL];       // (B,S,H*dk)

// ---------------- helpers ----------------
__device__ __forceinline__ uint32_t smem_u32(const void* p) {
    uint32_t a;
    asm("{ .reg .u64 t; cvta.to.shared.u64 t, %1; cvt.u32.u64 %0, t; }"
        : "=r"(a) : "l"(p));
    return a;
}

__device__ __forceinline__ uint32_t f2tf(float x) {
    uint32_t r;
    asm("cvt.rna.tf32.f32 %0, %1;" : "=r"(r) : "f"(x));
    return r;
}

// D += A(m16k8, tf32) * B(k8n8, tf32)   (row.col)
__device__ __forceinline__ void mma_tf32(float* c, const uint32_t* a, const uint32_t* b) {
    asm volatile(
        "mma.sync.aligned.m16n8k8.row.col.f32.tf32.tf32.f32 "
        "{%0,%1,%2,%3},{%4,%5,%6,%7},{%8,%9},{%0,%1,%2,%3};"
        : "+f"(c[0]), "+f"(c[1]), "+f"(c[2]), "+f"(c[3])
        : "r"(a[0]), "r"(a[1]), "r"(a[2]), "r"(a[3]), "r"(b[0]), "r"(b[1]));
}

#define CP_ASYNC16(dst, src) \
    asm volatile("cp.async.cg.shared.global [%0], [%1], 16;" :: "r"(dst), "l"(src) : "memory")
#define CP_COMMIT() asm volatile("cp.async.commit_group;" ::: "memory")
#define CP_WAIT1()  asm volatile("cp.async.wait_group 1;" ::: "memory")

// ============================================================================
// tf32 mma.sync GEMM-NT:  C[m,n] = sum_k A[m,k] * W[n,k] + bias[n]
//   128x128 block, BK=32, 256 threads (8 warps, 2m x 4n grid, 64x32 warp tile)
//   cp.async double buffering. mode 0: head-split out; mode 1: row-major out.
// ============================================================================
#define GS 36                                   // padded row stride (floats)
#define GEMM_SMEM (2 * 2 * 128 * GS * 4)        // 73728 B

__device__ __forceinline__ void gemm_load_stage(uint32_t sbase, uint32_t woffB,
                                                const float* __restrict__ Ag,
                                                const float* __restrict__ Wg,
                                                int s, int k0, int tid)
{
#pragma unroll
    for (int i = 0; i < 4; i++) {
        int idx = tid + 256 * i;                // 0..1023
        int r   = idx >> 3;                     // 0..127
        int c4  = (idx & 7) << 2;               // 0,4,..,28
        uint32_t d = (uint32_t)(((s * 128 + r) * GS + c4) * 4);
        CP_ASYNC16(sbase + d,         Ag + (size_t)r * DMODEL + k0 + c4);
        CP_ASYNC16(sbase + woffB + d, Wg + (size_t)r * DMODEL + k0 + c4);
    }
}

__global__ __launch_bounds__(256)
void gemm_mma(const float* __restrict__ A, const float* __restrict__ W,
              const float* __restrict__ bias, float* __restrict__ C, int mode)
{
    extern __shared__ float sm[];
    const float* As  = sm;                       // [2][128][GS]
    const float* Ws_ = sm + 2 * 128 * GS;        // [2][128][GS]
    const uint32_t sbase = smem_u32(sm);
    const uint32_t woffB = (uint32_t)(2 * 128 * GS * 4);

    const int tid  = threadIdx.x;
    const int lane = tid & 31, wid = tid >> 5;
    const int wm = wid >> 2, wn = wid & 3;       // warp grid 2 x 4
    const int r0 = lane >> 2, c0 = lane & 3;

    const int rowBase = blockIdx.y * 128;
    const int colBase = blockIdx.x * 128;
    const float* Ag = A + (size_t)rowBase * DMODEL;
    const float* Wg = W + (size_t)colBase * DMODEL;

    float acc[4][4][4];
#pragma unroll
    for (int mf = 0; mf < 4; mf++)
#pragma unroll
        for (int nf = 0; nf < 4; nf++)
#pragma unroll
            for (int r = 0; r < 4; r++) acc[mf][nf][r] = 0.f;

    gemm_load_stage(sbase, woffB, Ag, Wg, 0, 0, tid);  CP_COMMIT();
    gemm_load_stage(sbase, woffB, Ag, Wg, 1, 32, tid); CP_COMMIT();

    for (int kt = 0; kt < DMODEL / 32; kt++) {
        CP_WAIT1();
        __syncthreads();
        const float* as = As  + (kt & 1) * 128 * GS;
        const float* ws = Ws_ + (kt & 1) * 128 * GS;
#pragma unroll
        for (int ks = 0; ks < 4; ks++) {
            const int kc = ks * 8;
            uint32_t af[4][4], bf[4][2];
#pragma unroll
            for (int mf = 0; mf < 4; mf++) {
                const float* ap = as + (wm * 64 + mf * 16 + r0) * GS + kc + c0;
                af[mf][0] = f2tf(ap[0]);
                af[mf][1] = f2tf(ap[8 * GS]);
                af[mf][2] = f2tf(ap[4]);
                af[mf][3] = f2tf(ap[8 * GS + 4]);
            }
#pragma unroll
            for (int nf = 0; nf < 4; nf++) {
                const float* wp = ws + (wn * 32 + nf * 8 + r0) * GS + kc + c0;
                bf[nf][0] = f2tf(wp[0]);
                bf[nf][1] = f2tf(wp[4]);
            }
#pragma unroll
            for (int mf = 0; mf < 4; mf++)
#pragma unroll
                for (int nf = 0; nf < 4; nf++)
                    mma_tf32(acc[mf][nf], af[mf], bf[nf]);
        }
        __syncthreads();
        if (kt + 2 < DMODEL / 32)
            gemm_load_stage(sbase, woffB, Ag, Wg, kt & 1, (kt + 2) * 32, tid);
        CP_COMMIT();
    }

    // epilogue
#pragma unroll
    for (int mf = 0; mf < 4; mf++) {
        const int m0 = rowBase + wm * 64 + mf * 16 + r0;
        const int m1 = m0 + 8;
#pragma unroll
        for (int nf = 0; nf < 4; nf++) {
            const int n = colBase + wn * 32 + nf * 8 + 2 * c0;
            float2 v0, v1;
            v0.x = acc[mf][nf][0] + bias[n];
            v0.y = acc[mf][nf][1] + bias[n + 1];
            v1.x = acc[mf][nf][2] + bias[n];
            v1.y = acc[mf][nf][3] + bias[n + 1];
            if (mode == 1) {
                *(float2*)(C + (size_t)m0 * DMODEL + n) = v0;
                *(float2*)(C + (size_t)m1 * DMODEL + n) = v1;
            } else {
                const int hh = n >> 6, dd = n & 63;
                const int b0 = m0 >> 11, s0 = m0 & (SEQ - 1);
                const int b1 = m1 >> 11, s1 = m1 & (SEQ - 1);
                *(float2*)(C + ((((size_t)b0 * H_HEADS + hh) * SEQ + s0) << 6) + dd) = v0;
                *(float2*)(C + ((((size_t)b1 * H_HEADS + hh) * SEQ + s1) << 6) + dd) = v1;
            }
        }
    }
}

// ============================================================================
// Flash attention with tf32 mma.sync.
//   Block = 128 threads (4 warps), q-tile 64 (warp owns 16 q rows), k-tile 64.
//   Q,K,P strides 68 (==4 mod 32), V stride 72 (==8 mod 32): conflict-free
//   fragment LDS. P round-trips through warp-private smem between QK and PV.
// ============================================================================
#define QST 68
#define VST 72
#define ATT_SMEM ((3 * 64 * QST + 64 * VST + 64) * 4)   // 70912 B

__global__ __launch_bounds__(128)
void attn_mma(const float* __restrict__ Q, const float* __restrict__ Kg_,
              const float* __restrict__ Vg_, const int* __restrict__ mask,
              float* __restrict__ ctx)
{
    extern __shared__ float sm[];
    float* Qs = sm;                       // [64][QST]
    float* Ks = sm + 64 * QST;            // [64][QST]
    float* Ps = sm + 2 * 64 * QST;        // [64][QST]
    float* Vs = sm + 3 * 64 * QST;        // [64][VST]
    int*   Ms = (int*)(sm + 3 * 64 * QST + 64 * VST);

    const int tid  = threadIdx.x;
    const int lane = tid & 31, wid = tid >> 5;
    const int r0 = lane >> 2, c0 = lane & 3;
    const int qt = blockIdx.x, h = blockIdx.y, b = blockIdx.z;

    const size_t bh = (size_t)b * H_HEADS + h;
    const float* Qg = Q   + (bh * SEQ + (size_t)qt * 64) * 64;
    const float* Kg = Kg_ + bh * SEQ * 64;
    const float* Vg = Vg_ + bh * SEQ * 64;
    const int*   mg = mask + (size_t)b * SEQ;

    // load Q tile (row-major, stride QST)
#pragma unroll
    for (int i = 0; i < 8; i++) {
        int idx = tid + 128 * i;
        int q = idx >> 4, d4 = (idx & 15) << 2;
        *(float4*)&Qs[q * QST + d4] = *(const float4*)(Qg + (size_t)q * 64 + d4);
    }

    float o[8][4];
#pragma unroll
    for (int nf = 0; nf < 8; nf++)
#pragma unroll
        for (int r = 0; r < 4; r++) o[nf][r] = 0.f;
    float mprev0 = -1e30f, mprev1 = -1e30f, lsum0 = 0.f, lsum1 = 0.f;

    const int qrow = wid * 16 + r0;       // local q row of c0/c1 regs

    for (int kt = 0; kt < SEQ / 64; kt++) {
        __syncthreads();
#pragma unroll
        for (int i = 0; i < 8; i++) {
            int idx = tid + 128 * i;
            int r = idx >> 4, d4 = (idx & 15) << 2;
            *(float4*)&Ks[r * QST + d4] =
                *(const float4*)(Kg + ((size_t)kt * 64 + r) * 64 + d4);
            *(float4*)&Vs[r * VST + d4] =
                *(const float4*)(Vg + ((size_t)kt * 64 + r) * 64 + d4);
        }
        if (tid < 64) Ms[tid] = mg[kt * 64 + tid];
        __syncthreads();

        // -------- S = Q . K^T --------
        float s[8][4];
#pragma unroll
        for (int nf = 0; nf < 8; nf++)
#pragma unroll
            for (int r = 0; r < 4; r++) s[nf][r] = 0.f;

#pragma unroll
        for (int ks = 0; ks < 8; ks++) {
            const int kc = ks * 8;
            uint32_t a[4];
            const float* ap = Qs + qrow * QST + kc + c0;
            a[0] = f2tf(ap[0]);
            a[1] = f2tf(ap[8 * QST]);
            a[2] = f2tf(ap[4]);
            a[3] = f2tf(ap[8 * QST + 4]);
#pragma unroll
            for (int nf = 0; nf < 8; nf++) {
                uint32_t bb[2];
                const float* bp = Ks + (nf * 8 + r0) * QST + kc + c0;
                bb[0] = f2tf(bp[0]);
                bb[1] = f2tf(bp[4]);
                mma_tf32(s[nf], a, bb);
            }
        }

        // -------- scale + mask + online softmax --------
        float rmax0 = -1e30f, rmax1 = -1e30f;
#pragma unroll
        for (int nf = 0; nf < 8; nf++) {
            const int nc = nf * 8 + 2 * c0;
            const bool k0m = Ms[nc] != 0, k1m = Ms[nc + 1] != 0;
            s[nf][0] = k0m ? s[nf][0] * 0.125f : -1e9f;
            s[nf][1] = k1m ? s[nf][1] * 0.125f : -1e9f;
            s[nf][2] = k0m ? s[nf][2] * 0.125f : -1e9f;
            s[nf][3] = k1m ? s[nf][3] * 0.125f : -1e9f;
            rmax0 = fmaxf(rmax0, fmaxf(s[nf][0], s[nf][1]));
            rmax1 = fmaxf(rmax1, fmaxf(s[nf][2], s[nf][3]));
        }
        rmax0 = fmaxf(rmax0, __shfl_xor_sync(0xffffffffu, rmax0, 1));
        rmax0 = fmaxf(rmax0, __shfl_xor_sync(0xffffffffu, rmax0, 2));
        rmax1 = fmaxf(rmax1, __shfl_xor_sync(0xffffffffu, rmax1, 1));
        rmax1 = fmaxf(rmax1, __shfl_xor_sync(0xffffffffu, rmax1, 2));

        const float mn0 = fmaxf(mprev0, rmax0);
        const float mn1 = fmaxf(mprev1, rmax1);
        const float fac0 = __expf(mprev0 - mn0);
        const float fac1 = __expf(mprev1 - mn1);

        float rs0 = 0.f, rs1 = 0.f;
#pragma unroll
        for (int nf = 0; nf < 8; nf++) {
            s[nf][0] = __expf(s[nf][0] - mn0);
            s[nf][1] = __expf(s[nf][1] - mn0);
            s[nf][2] = __expf(s[nf][2] - mn1);
            s[nf][3] = __expf(s[nf][3] - mn1);
            rs0 += s[nf][0] + s[nf][1];
            rs1 += s[nf][2] + s[nf][3];
        }
        rs0 += __shfl_xor_sync(0xffffffffu, rs0, 1);
        rs0 += __shfl_xor_sync(0xffffffffu, rs0, 2);
        rs1 += __shfl_xor_sync(0xffffffffu, rs1, 1);
        rs1 += __shfl_xor_sync(0xffffffffu, rs1, 2);

        lsum0 = lsum0 * fac0 + rs0;
        lsum1 = lsum1 * fac1 + rs1;
        mprev0 = mn0; mprev1 = mn1;
#pragma unroll
        for (int nf = 0; nf < 8; nf++) {
            o[nf][0] *= fac0; o[nf][1] *= fac0;
            o[nf][2] *= fac1; o[nf][3] *= fac1;
        }

        // stage P (warp-private rows)
#pragma unroll
        for (int nf = 0; nf < 8; nf++) {
            float2 p0 = {s[nf][0], s[nf][1]};
            float2 p1 = {s[nf][2], s[nf][3]};
            *(float2*)&Ps[qrow * QST + nf * 8 + 2 * c0] = p0;
            *(float2*)&Ps[(qrow + 8) * QST + nf * 8 + 2 * c0] = p1;
        }
        __syncwarp();

        // -------- O += P . V --------
#pragma unroll
        for (int ks = 0; ks < 8; ks++) {
            const int kc = ks * 8;
            uint32_t a[4];
            const float* pp = Ps + qrow * QST + kc + c0;
            a[0] = f2tf(pp[0]);
            a[1] = f2tf(pp[8 * QST]);
            a[2] = f2tf(pp[4]);
            a[3] = f2tf(pp[8 * QST + 4]);
#pragma unroll
            for (int nf = 0; nf < 8; nf++) {
                uint32_t bb[2];
                const float* vp = Vs + (kc + c0) * VST + nf * 8 + r0;
                bb[0] = f2tf(vp[0]);
                bb[1] = f2tf(vp[4 * VST]);
                mma_tf32(o[nf], a, bb);
            }
        }
        __syncwarp();
    }

    // finalize: ctx (B,S,H,64)
    const float inv0 = (lsum0 > 0.f) ? (1.f / lsum0) : 0.f;
    const float inv1 = (lsum1 > 0.f) ? (1.f / lsum1) : 0.f;
    const int q0 = qt * 64 + qrow;
#pragma unroll
    for (int nf = 0; nf < 8; nf++) {
        const int d = nf * 8 + 2 * c0;
        float2 v0 = {o[nf][0] * inv0, o[nf][1] * inv0};
        float2 v1 = {o[nf][2] * inv1, o[nf][3] * inv1};
        *(float2*)(ctx + ((size_t)(b * SEQ + q0) * H_HEADS + h) * 64 + d) = v0;
        *(float2*)(ctx + ((size_t)(b * SEQ + q0 + 8) * H_HEADS + h) * 64 + d) = v1;
    }
}

// ============================================================================
// launch
// ============================================================================
extern "C" void kernel_launch(void* const* d_in, const int* in_sizes, int n_in,
                              void* d_out, int out_size)
{
    const float* query = (const float*)d_in[0];
    const float* key_  = (const float*)d_in[1];
    const float* value = (const float*)d_in[2];
    const int*   mask  = (const int*)  d_in[3];
    const float* Wq = (const float*)d_in[4];
    const float* bq = (const float*)d_in[5];
    const float* Wk = (const float*)d_in[6];
    const float* bk = (const float*)d_in[7];
    const float* Wv = (const float*)d_in[8];
    const float* bv = (const float*)d_in[9];
    const float* Wo = (const float*)d_in[10];
    const float* bo = (const float*)d_in[11];
    float* out = (float*)d_out;

    float *gq, *gk, *gv, *gctx;
    cudaGetSymbolAddress((void**)&gq,  g_q);
    cudaGetSymbolAddress((void**)&gk,  g_k);
    cudaGetSymbolAddress((void**)&gv,  g_v);
    cudaGetSymbolAddress((void**)&gctx, g_ctx);

    cudaFuncSetAttribute(gemm_mma,
                         cudaFuncAttributeMaxDynamicSharedMemorySize, GEMM_SMEM);
    cudaFuncSetAttribute(attn_mma,
                         cudaFuncAttributeMaxDynamicSharedMemorySize, ATT_SMEM);

    const int M = BATCH * SEQ;                 // 8192
    dim3 ggrid(DMODEL / 128, M / 128);         // (8, 64)
    dim3 gblock(256);

    gemm_mma<<<ggrid, gblock, GEMM_SMEM>>>(query, Wq, bq, gq, 0);
    gemm_mma<<<ggrid, gblock, GEMM_SMEM>>>(key_,  Wk, bk, gk, 0);
    gemm_mma<<<ggrid, gblock, GEMM_SMEM>>>(value, Wv, bv, gv, 0);

    dim3 agrid(SEQ / 64, H_HEADS, BATCH);      // (32, 16, 4)
    attn_mma<<<agrid, dim3(128), ATT_SMEM>>>(gq, gk, gv, mask, gctx);

    gemm_mma<<<ggrid, gblock, GEMM_SMEM>>>(gctx, Wo, bo, out, 1);
}

// round 4
// speedup vs baseline: 3.1742x; 1.0533x over previous
#include <cuda_runtime.h>
#include <cstdint>

// ---------------- problem constants ----------------
#define H_HEADS 16
#define DMODEL  1024
#define BATCH   4
#define SEQ     2048

// ---------------- scratch (static device globals; no allocs) ----------------
__device__ float g_q[(size_t)BATCH * H_HEADS * SEQ * 64];   // (B,H,S,dk) tf32-rounded, pre-scaled
__device__ float g_k[(size_t)BATCH * H_HEADS * SEQ * 64];   // tf32-rounded
__device__ float g_v[(size_t)BATCH * H_HEADS * SEQ * 64];   // tf32-rounded
__device__ float g_ctx[(size_t)BATCH * SEQ * DMODEL];       // (B,S,H*dk)

// ---------------- helpers ----------------
__device__ __forceinline__ uint32_t smem_u32(const void* p) {
    uint32_t a;
    asm("{ .reg .u64 t; cvta.to.shared.u64 t, %1; cvt.u32.u64 %0, t; }"
        : "=r"(a) : "l"(p));
    return a;
}

__device__ __forceinline__ uint32_t f2tf(float x) {
    uint32_t r;
    asm("cvt.rna.tf32.f32 %0, %1;" : "=r"(r) : "f"(x));
    return r;
}

// D += A(m16k8, tf32) * B(k8n8, tf32)   (row.col)
__device__ __forceinline__ void mma_tf32(float* c, const uint32_t* a, const uint32_t* b) {
    asm volatile(
        "mma.sync.aligned.m16n8k8.row.col.f32.tf32.tf32.f32 "
        "{%0,%1,%2,%3},{%4,%5,%6,%7},{%8,%9},{%0,%1,%2,%3};"
        : "+f"(c[0]), "+f"(c[1]), "+f"(c[2]), "+f"(c[3])
        : "r"(a[0]), "r"(a[1]), "r"(a[2]), "r"(a[3]), "r"(b[0]), "r"(b[1]));
}

#define CP_ASYNC16(dst, src) \
    asm volatile("cp.async.cg.shared.global [%0], [%1], 16;" :: "r"(dst), "l"(src) : "memory")
#define CP_ASYNC4(dst, src) \
    asm volatile("cp.async.ca.shared.global [%0], [%1], 4;" :: "r"(dst), "l"(src) : "memory")
#define CP_COMMIT() asm volatile("cp.async.commit_group;" ::: "memory")
#define CP_WAIT1()  asm volatile("cp.async.wait_group 1;" ::: "memory")
#define CP_WAIT0()  asm volatile("cp.async.wait_group 0;" ::: "memory")

// ============================================================================
// tf32 mma.sync GEMM-NT:  C[m,n] = sum_k A[m,k] * W[n,k] + bias[n]
//   128x128 block, BK=32, 256 threads (8 warps, 2m x 4n grid, 64x32 warp tile)
//   cp.async double buffering.
//   mode 0: head-split out, tf32-rounded        (K, V)
//   mode 2: head-split out, tf32-rounded, x1/8  (Q)
//   mode 1: plain row-major out, full fp32      (final output)
// ============================================================================
#define GS 36                                   // padded row stride (floats)
#define GEMM_SMEM (2 * 2 * 128 * GS * 4)        // 73728 B

__device__ __forceinline__ void gemm_load_stage(uint32_t sbase, uint32_t woffB,
                                                const float* __restrict__ Ag,
                                                const float* __restrict__ Wg,
                                                int s, int k0, int tid)
{
#pragma unroll
    for (int i = 0; i < 4; i++) {
        int idx = tid + 256 * i;                // 0..1023
        int r   = idx >> 3;                     // 0..127
        int c4  = (idx & 7) << 2;               // 0,4,..,28
        uint32_t d = (uint32_t)(((s * 128 + r) * GS + c4) * 4);
        CP_ASYNC16(sbase + d,         Ag + (size_t)r * DMODEL + k0 + c4);
        CP_ASYNC16(sbase + woffB + d, Wg + (size_t)r * DMODEL + k0 + c4);
    }
}

__global__ __launch_bounds__(256)
void gemm_mma(const float* __restrict__ A, const float* __restrict__ W,
              const float* __restrict__ bias, float* __restrict__ C, int mode)
{
    extern __shared__ float sm[];
    const float* As  = sm;                       // [2][128][GS]
    const float* Ws_ = sm + 2 * 128 * GS;        // [2][128][GS]
    const uint32_t sbase = smem_u32(sm);
    const uint32_t woffB = (uint32_t)(2 * 128 * GS * 4);

    const int tid  = threadIdx.x;
    const int lane = tid & 31, wid = tid >> 5;
    const int wm = wid >> 2, wn = wid & 3;       // warp grid 2 x 4
    const int r0 = lane >> 2, c0 = lane & 3;

    const int rowBase = blockIdx.y * 128;
    const int colBase = blockIdx.x * 128;
    const float* Ag = A + (size_t)rowBase * DMODEL;
    const float* Wg = W + (size_t)colBase * DMODEL;

    float acc[4][4][4];
#pragma unroll
    for (int mf = 0; mf < 4; mf++)
#pragma unroll
        for (int nf = 0; nf < 4; nf++)
#pragma unroll
            for (int r = 0; r < 4; r++) acc[mf][nf][r] = 0.f;

    gemm_load_stage(sbase, woffB, Ag, Wg, 0, 0, tid);  CP_COMMIT();
    gemm_load_stage(sbase, woffB, Ag, Wg, 1, 32, tid); CP_COMMIT();

    for (int kt = 0; kt < DMODEL / 32; kt++) {
        CP_WAIT1();
        __syncthreads();
        const float* as = As  + (kt & 1) * 128 * GS;
        const float* ws = Ws_ + (kt & 1) * 128 * GS;
#pragma unroll
        for (int ks = 0; ks < 4; ks++) {
            const int kc = ks * 8;
            uint32_t af[4][4], bf[4][2];
#pragma unroll
            for (int mf = 0; mf < 4; mf++) {
                const float* ap = as + (wm * 64 + mf * 16 + r0) * GS + kc + c0;
                af[mf][0] = f2tf(ap[0]);
                af[mf][1] = f2tf(ap[8 * GS]);
                af[mf][2] = f2tf(ap[4]);
                af[mf][3] = f2tf(ap[8 * GS + 4]);
            }
#pragma unroll
            for (int nf = 0; nf < 4; nf++) {
                const float* wp = ws + (wn * 32 + nf * 8 + r0) * GS + kc + c0;
                bf[nf][0] = f2tf(wp[0]);
                bf[nf][1] = f2tf(wp[4]);
            }
#pragma unroll
            for (int mf = 0; mf < 4; mf++)
#pragma unroll
                for (int nf = 0; nf < 4; nf++)
                    mma_tf32(acc[mf][nf], af[mf], bf[nf]);
        }
        __syncthreads();
        if (kt + 2 < DMODEL / 32)
            gemm_load_stage(sbase, woffB, Ag, Wg, kt & 1, (kt + 2) * 32, tid);
        CP_COMMIT();
    }

    // epilogue
    const float oscale = (mode == 2) ? 0.125f : 1.0f;
#pragma unroll
    for (int mf = 0; mf < 4; mf++) {
        const int m0 = rowBase + wm * 64 + mf * 16 + r0;
        const int m1 = m0 + 8;
#pragma unroll
        for (int nf = 0; nf < 4; nf++) {
            const int n = colBase + wn * 32 + nf * 8 + 2 * c0;
            float2 v0, v1;
            v0.x = acc[mf][nf][0] + bias[n];
            v0.y = acc[mf][nf][1] + bias[n + 1];
            v1.x = acc[mf][nf][2] + bias[n];
            v1.y = acc[mf][nf][3] + bias[n + 1];
            if (mode == 1) {
                *(float2*)(C + (size_t)m0 * DMODEL + n) = v0;
                *(float2*)(C + (size_t)m1 * DMODEL + n) = v1;
            } else {
                // pre-round to tf32 (and pre-scale for Q) so attention needs no cvt
                v0.x = __uint_as_float(f2tf(v0.x * oscale));
                v0.y = __uint_as_float(f2tf(v0.y * oscale));
                v1.x = __uint_as_float(f2tf(v1.x * oscale));
                v1.y = __uint_as_float(f2tf(v1.y * oscale));
                const int hh = n >> 6, dd = n & 63;
                const int b0 = m0 >> 11, s0 = m0 & (SEQ - 1);
                const int b1 = m1 >> 11, s1 = m1 & (SEQ - 1);
                *(float2*)(C + ((((size_t)b0 * H_HEADS + hh) * SEQ + s0) << 6) + dd) = v0;
                *(float2*)(C + ((((size_t)b1 * H_HEADS + hh) * SEQ + s1) << 6) + dd) = v1;
            }
        }
    }
}

// ============================================================================
// Flash attention with tf32 mma.sync.
//   Block = 128 threads (4 warps), q-tile 64 (warp owns 16 q rows), k-tile 64.
//   Q/K/V arrive tf32-pre-rounded (and Q pre-scaled) -> fragment loads are
//   plain bit reinterprets. K/V/mask double-buffered via cp.async.
// ============================================================================
#define QST 68
#define VST 72
// Qs[64][QST] + Ks[2][64][QST] + Vs[2][64][VST] + Ps[64][QST] + Ms[2][64]
#define ATT_SMEM ((4 * 64 * QST + 2 * 64 * VST + 128) * 4)   // 107008 B

__device__ __forceinline__ void attn_fill(uint32_t kb, uint32_t vb, uint32_t mb,
                                          const float* __restrict__ Kg,
                                          const float* __restrict__ Vg,
                                          const int* __restrict__ mg,
                                          int kt, int tid)
{
#pragma unroll
    for (int i = 0; i < 8; i++) {
        int idx = tid + 128 * i;
        int r = idx >> 4, d4 = (idx & 15) << 2;
        CP_ASYNC16(kb + (uint32_t)((r * QST + d4) * 4),
                   Kg + ((size_t)kt * 64 + r) * 64 + d4);
        CP_ASYNC16(vb + (uint32_t)((r * VST + d4) * 4),
                   Vg + ((size_t)kt * 64 + r) * 64 + d4);
    }
    if (tid < 64) CP_ASYNC4(mb + (uint32_t)(tid * 4), mg + kt * 64 + tid);
}

__global__ __launch_bounds__(128)
void attn_mma(const float* __restrict__ Q, const float* __restrict__ Kg_,
              const float* __restrict__ Vg_, const int* __restrict__ mask,
              float* __restrict__ ctx)
{
    extern __shared__ float sm[];
    float* Qs = sm;                             // [64][QST]
    float* Ks = sm + 64 * QST;                  // [2][64][QST]
    float* Vs = sm + 3 * 64 * QST;              // [2][64][VST]
    float* Ps = sm + 3 * 64 * QST + 2 * 64 * VST;  // [64][QST]
    int*   Ms = (int*)(Ps + 64 * QST);          // [2][64]

    const uint32_t sb = smem_u32(sm);
    const uint32_t KsB = sb + 64 * QST * 4;
    const uint32_t VsB = sb + 3 * 64 * QST * 4;
    const uint32_t MsB = sb + (4 * 64 * QST + 2 * 64 * VST) * 4;

    const int tid  = threadIdx.x;
    const int lane = tid & 31, wid = tid >> 5;
    const int r0 = lane >> 2, c0 = lane & 3;
    const int qt = blockIdx.x, h = blockIdx.y, b = blockIdx.z;

    const size_t bh = (size_t)b * H_HEADS + h;
    const float* Qg = Q   + (bh * SEQ + (size_t)qt * 64) * 64;
    const float* Kg = Kg_ + bh * SEQ * 64;
    const float* Vg = Vg_ + bh * SEQ * 64;
    const int*   mg = mask + (size_t)b * SEQ;

    // load Q tile (row-major, stride QST)
#pragma unroll
    for (int i = 0; i < 8; i++) {
        int idx = tid + 128 * i;
        int q = idx >> 4, d4 = (idx & 15) << 2;
        *(float4*)&Qs[q * QST + d4] = *(const float4*)(Qg + (size_t)q * 64 + d4);
    }

    float o[8][4];
#pragma unroll
    for (int nf = 0; nf < 8; nf++)
#pragma unroll
        for (int r = 0; r < 4; r++) o[nf][r] = 0.f;
    float mprev0 = -1e30f, mprev1 = -1e30f, lsum0 = 0.f, lsum1 = 0.f;

    const int qrow = wid * 16 + r0;

    // prologue: fill stage 0
    attn_fill(KsB, VsB, MsB, Kg, Vg, mg, 0, tid);
    CP_COMMIT();

    const int nkt = SEQ / 64;
    for (int kt = 0; kt < nkt; kt++) {
        CP_WAIT0();
        __syncthreads();

        const int cur = kt & 1;
        if (kt + 1 < nkt) {
            const int nxt = (kt + 1) & 1;
            attn_fill(KsB + (uint32_t)(nxt * 64 * QST * 4),
                      VsB + (uint32_t)(nxt * 64 * VST * 4),
                      MsB + (uint32_t)(nxt * 256),
                      Kg, Vg, mg, kt + 1, tid);
        }
        CP_COMMIT();

        const float* ks_ = Ks + cur * 64 * QST;
        const float* vs_ = Vs + cur * 64 * VST;
        const int*   ms_ = Ms + cur * 64;

        // -------- S = Q . K^T  (Q pre-scaled by 1/8, both tf32-rounded) ----
        float s[8][4];
#pragma unroll
        for (int nf = 0; nf < 8; nf++)
#pragma unroll
            for (int r = 0; r < 4; r++) s[nf][r] = 0.f;

#pragma unroll
        for (int ks = 0; ks < 8; ks++) {
            const int kc = ks * 8;
            uint32_t a[4];
            const float* ap = Qs + qrow * QST + kc + c0;
            a[0] = __float_as_uint(ap[0]);
            a[1] = __float_as_uint(ap[8 * QST]);
            a[2] = __float_as_uint(ap[4]);
            a[3] = __float_as_uint(ap[8 * QST + 4]);
#pragma unroll
            for (int nf = 0; nf < 8; nf++) {
                uint32_t bb[2];
                const float* bp = ks_ + (nf * 8 + r0) * QST + kc + c0;
                bb[0] = __float_as_uint(bp[0]);
                bb[1] = __float_as_uint(bp[4]);
                mma_tf32(s[nf], a, bb);
            }
        }

        // -------- mask + online softmax --------
        float rmax0 = -1e30f, rmax1 = -1e30f;
#pragma unroll
        for (int nf = 0; nf < 8; nf++) {
            const int nc = nf * 8 + 2 * c0;
            const bool k0m = ms_[nc] != 0, k1m = ms_[nc + 1] != 0;
            s[nf][0] = k0m ? s[nf][0] : -1e9f;
            s[nf][1] = k1m ? s[nf][1] : -1e9f;
            s[nf][2] = k0m ? s[nf][2] : -1e9f;
            s[nf][3] = k1m ? s[nf][3] : -1e9f;
            rmax0 = fmaxf(rmax0, fmaxf(s[nf][0], s[nf][1]));
            rmax1 = fmaxf(rmax1, fmaxf(s[nf][2], s[nf][3]));
        }
        rmax0 = fmaxf(rmax0, __shfl_xor_sync(0xffffffffu, rmax0, 1));
        rmax0 = fmaxf(rmax0, __shfl_xor_sync(0xffffffffu, rmax0, 2));
        rmax1 = fmaxf(rmax1, __shfl_xor_sync(0xffffffffu, rmax1, 1));
        rmax1 = fmaxf(rmax1, __shfl_xor_sync(0xffffffffu, rmax1, 2));

        const float mn0 = fmaxf(mprev0, rmax0);
        const float mn1 = fmaxf(mprev1, rmax1);
        const float fac0 = __expf(mprev0 - mn0);
        const float fac1 = __expf(mprev1 - mn1);

        float rs0 = 0.f, rs1 = 0.f;
#pragma unroll
        for (int nf = 0; nf < 8; nf++) {
            s[nf][0] = __expf(s[nf][0] - mn0);
            s[nf][1] = __expf(s[nf][1] - mn0);
            s[nf][2] = __expf(s[nf][2] - mn1);
            s[nf][3] = __expf(s[nf][3] - mn1);
            rs0 += s[nf][0] + s[nf][1];
            rs1 += s[nf][2] + s[nf][3];
        }
        rs0 += __shfl_xor_sync(0xffffffffu, rs0, 1);
        rs0 += __shfl_xor_sync(0xffffffffu, rs0, 2);
        rs1 += __shfl_xor_sync(0xffffffffu, rs1, 1);
        rs1 += __shfl_xor_sync(0xffffffffu, rs1, 2);

        lsum0 = lsum0 * fac0 + rs0;
        lsum1 = lsum1 * fac1 + rs1;
        mprev0 = mn0; mprev1 = mn1;
#pragma unroll
        for (int nf = 0; nf < 8; nf++) {
            o[nf][0] *= fac0; o[nf][1] *= fac0;
            o[nf][2] *= fac1; o[nf][3] *= fac1;
        }

        // stage P (warp-private rows), pre-rounded to tf32 at store
#pragma unroll
        for (int nf = 0; nf < 8; nf++) {
            float2 p0 = {__uint_as_float(f2tf(s[nf][0])), __uint_as_float(f2tf(s[nf][1]))};
            float2 p1 = {__uint_as_float(f2tf(s[nf][2])), __uint_as_float(f2tf(s[nf][3]))};
            *(float2*)&Ps[qrow * QST + nf * 8 + 2 * c0] = p0;
            *(float2*)&Ps[(qrow + 8) * QST + nf * 8 + 2 * c0] = p1;
        }
        __syncwarp();

        // -------- O += P . V --------
#pragma unroll
        for (int ks = 0; ks < 8; ks++) {
            const int kc = ks * 8;
            uint32_t a[4];
            const float* pp = Ps + qrow * QST + kc + c0;
            a[0] = __float_as_uint(pp[0]);
            a[1] = __float_as_uint(pp[8 * QST]);
            a[2] = __float_as_uint(pp[4]);
            a[3] = __float_as_uint(pp[8 * QST + 4]);
#pragma unroll
            for (int nf = 0; nf < 8; nf++) {
                uint32_t bb[2];
                const float* vp = vs_ + (kc + c0) * VST + nf * 8 + r0;
                bb[0] = __float_as_uint(vp[0]);
                bb[1] = __float_as_uint(vp[4 * VST]);
                mma_tf32(o[nf], a, bb);
            }
        }
        __syncwarp();
    }

    // finalize: ctx (B,S,H,64)
    const float inv0 = (lsum0 > 0.f) ? (1.f / lsum0) : 0.f;
    const float inv1 = (lsum1 > 0.f) ? (1.f / lsum1) : 0.f;
    const int q0 = qt * 64 + qrow;
#pragma unroll
    for (int nf = 0; nf < 8; nf++) {
        const int d = nf * 8 + 2 * c0;
        float2 v0 = {o[nf][0] * inv0, o[nf][1] * inv0};
        float2 v1 = {o[nf][2] * inv1, o[nf][3] * inv1};
        *(float2*)(ctx + ((size_t)(b * SEQ + q0) * H_HEADS + h) * 64 + d) = v0;
        *(float2*)(ctx + ((size_t)(b * SEQ + q0 + 8) * H_HEADS + h) * 64 + d) = v1;
    }
}

// ============================================================================
// launch
// ============================================================================
extern "C" void kernel_launch(void* const* d_in, const int* in_sizes, int n_in,
                              void* d_out, int out_size)
{
    const float* query = (const float*)d_in[0];
    const float* key_  = (const float*)d_in[1];
    const float* value = (const float*)d_in[2];
    const int*   mask  = (const int*)  d_in[3];
    const float* Wq = (const float*)d_in[4];
    const float* bq = (const float*)d_in[5];
    const float* Wk = (const float*)d_in[6];
    const float* bk = (const float*)d_in[7];
    const float* Wv = (const float*)d_in[8];
    const float* bv = (const float*)d_in[9];
    const float* Wo = (const float*)d_in[10];
    const float* bo = (const float*)d_in[11];
    float* out = (float*)d_out;

    float *gq, *gk, *gv, *gctx;
    cudaGetSymbolAddress((void**)&gq,  g_q);
    cudaGetSymbolAddress((void**)&gk,  g_k);
    cudaGetSymbolAddress((void**)&gv,  g_v);
    cudaGetSymbolAddress((void**)&gctx, g_ctx);

    cudaFuncSetAttribute(gemm_mma,
                         cudaFuncAttributeMaxDynamicSharedMemorySize, GEMM_SMEM);
    cudaFuncSetAttribute(attn_mma,
                         cudaFuncAttributeMaxDynamicSharedMemorySize, ATT_SMEM);

    const int M = BATCH * SEQ;                 // 8192
    dim3 ggrid(DMODEL / 128, M / 128);         // (8, 64)
    dim3 gblock(256);

    gemm_mma<<<ggrid, gblock, GEMM_SMEM>>>(query, Wq, bq, gq, 2);  // Q: tf32 + 1/8
    gemm_mma<<<ggrid, gblock, GEMM_SMEM>>>(key_,  Wk, bk, gk, 0);  // K: tf32
    gemm_mma<<<ggrid, gblock, GEMM_SMEM>>>(value, Wv, bv, gv, 0);  // V: tf32

    dim3 agrid(SEQ / 64, H_HEADS, BATCH);      // (32, 16, 4)
    attn_mma<<<agrid, dim3(128), ATT_SMEM>>>(gq, gk, gv, mask, gctx);

    gemm_mma<<<ggrid, gblock, GEMM_SMEM>>>(gctx, Wo, bo, out, 1);
}

// round 5
// speedup vs baseline: 3.6958x; 1.1643x over previous
#include <cuda_runtime.h>
#include <cstdint>

// ---------------- problem constants ----------------
#define H_HEADS 16
#define DMODEL  1024
#define BATCH   4
#define SEQ     2048

// ---------------- scratch (static device globals; no allocs) ----------------
__device__ float g_q[(size_t)BATCH * H_HEADS * SEQ * 64];   // tf32-rounded, pre-scaled 1/8
__device__ float g_k[(size_t)BATCH * H_HEADS * SEQ * 64];   // tf32-rounded
__device__ float g_v[(size_t)BATCH * H_HEADS * SEQ * 64];   // tf32-rounded
__device__ float g_ctx[(size_t)BATCH * SEQ * DMODEL];       // (B,S,H*dk)

// ---------------- helpers ----------------
__device__ __forceinline__ uint32_t smem_u32(const void* p) {
    uint32_t a;
    asm("{ .reg .u64 t; cvta.to.shared.u64 t, %1; cvt.u32.u64 %0, t; }"
        : "=r"(a) : "l"(p));
    return a;
}

__device__ __forceinline__ uint32_t f2tf(float x) {
    uint32_t r;
    asm("cvt.rna.tf32.f32 %0, %1;" : "=r"(r) : "f"(x));
    return r;
}

// D += A(m16k8, tf32) * B(k8n8, tf32)   (row.col)
__device__ __forceinline__ void mma_tf32(float* c, const uint32_t* a, const uint32_t* b) {
    asm volatile(
        "mma.sync.aligned.m16n8k8.row.col.f32.tf32.tf32.f32 "
        "{%0,%1,%2,%3},{%4,%5,%6,%7},{%8,%9},{%0,%1,%2,%3};"
        : "+f"(c[0]), "+f"(c[1]), "+f"(c[2]), "+f"(c[3])
        : "r"(a[0]), "r"(a[1]), "r"(a[2]), "r"(a[3]), "r"(b[0]), "r"(b[1]));
}

#define CP_ASYNC16(dst, src) \
    asm volatile("cp.async.cg.shared.global [%0], [%1], 16;" :: "r"(dst), "l"(src) : "memory")
#define CP_ASYNC4(dst, src) \
    asm volatile("cp.async.ca.shared.global [%0], [%1], 4;" :: "r"(dst), "l"(src) : "memory")
#define CP_COMMIT() asm volatile("cp.async.commit_group;" ::: "memory")
#define CP_WAIT1()  asm volatile("cp.async.wait_group 1;" ::: "memory")
#define CP_WAIT0()  asm volatile("cp.async.wait_group 0;" ::: "memory")

// ============================================================================
// tf32 mma.sync GEMM-NT (unchanged from R4):
//   C[m,n] = sum_k A[m,k] * W[n,k] + bias[n]
//   mode 0: head-split out, tf32-rounded        (K, V)
//   mode 2: head-split out, tf32-rounded, x1/8  (Q)
//   mode 1: plain row-major out, full fp32      (final output)
// ============================================================================
#define GS 36
#define GEMM_SMEM (2 * 2 * 128 * GS * 4)        // 73728 B

__device__ __forceinline__ void gemm_load_stage(uint32_t sbase, uint32_t woffB,
                                                const float* __restrict__ Ag,
                                                const float* __restrict__ Wg,
                                                int s, int k0, int tid)
{
#pragma unroll
    for (int i = 0; i < 4; i++) {
        int idx = tid + 256 * i;
        int r   = idx >> 3;
        int c4  = (idx & 7) << 2;
        uint32_t d = (uint32_t)(((s * 128 + r) * GS + c4) * 4);
        CP_ASYNC16(sbase + d,         Ag + (size_t)r * DMODEL + k0 + c4);
        CP_ASYNC16(sbase + woffB + d, Wg + (size_t)r * DMODEL + k0 + c4);
    }
}

__global__ __launch_bounds__(256)
void gemm_mma(const float* __restrict__ A, const float* __restrict__ W,
              const float* __restrict__ bias, float* __restrict__ C, int mode)
{
    extern __shared__ float sm[];
    const float* As  = sm;
    const float* Ws_ = sm + 2 * 128 * GS;
    const uint32_t sbase = smem_u32(sm);
    const uint32_t woffB = (uint32_t)(2 * 128 * GS * 4);

    const int tid  = threadIdx.x;
    const int lane = tid & 31, wid = tid >> 5;
    const int wm = wid >> 2, wn = wid & 3;
    const int r0 = lane >> 2, c0 = lane & 3;

    const int rowBase = blockIdx.y * 128;
    const int colBase = blockIdx.x * 128;
    const float* Ag = A + (size_t)rowBase * DMODEL;
    const float* Wg = W + (size_t)colBase * DMODEL;

    float acc[4][4][4];
#pragma unroll
    for (int mf = 0; mf < 4; mf++)
#pragma unroll
        for (int nf = 0; nf < 4; nf++)
#pragma unroll
            for (int r = 0; r < 4; r++) acc[mf][nf][r] = 0.f;

    gemm_load_stage(sbase, woffB, Ag, Wg, 0, 0, tid);  CP_COMMIT();
    gemm_load_stage(sbase, woffB, Ag, Wg, 1, 32, tid); CP_COMMIT();

    for (int kt = 0; kt < DMODEL / 32; kt++) {
        CP_WAIT1();
        __syncthreads();
        const float* as = As  + (kt & 1) * 128 * GS;
        const float* ws = Ws_ + (kt & 1) * 128 * GS;
#pragma unroll
        for (int ks = 0; ks < 4; ks++) {
            const int kc = ks * 8;
            uint32_t af[4][4], bf[4][2];
#pragma unroll
            for (int mf = 0; mf < 4; mf++) {
                const float* ap = as + (wm * 64 + mf * 16 + r0) * GS + kc + c0;
                af[mf][0] = f2tf(ap[0]);
                af[mf][1] = f2tf(ap[8 * GS]);
                af[mf][2] = f2tf(ap[4]);
                af[mf][3] = f2tf(ap[8 * GS + 4]);
            }
#pragma unroll
            for (int nf = 0; nf < 4; nf++) {
                const float* wp = ws + (wn * 32 + nf * 8 + r0) * GS + kc + c0;
                bf[nf][0] = f2tf(wp[0]);
                bf[nf][1] = f2tf(wp[4]);
            }
#pragma unroll
            for (int mf = 0; mf < 4; mf++)
#pragma unroll
                for (int nf = 0; nf < 4; nf++)
                    mma_tf32(acc[mf][nf], af[mf], bf[nf]);
        }
        __syncthreads();
        if (kt + 2 < DMODEL / 32)
            gemm_load_stage(sbase, woffB, Ag, Wg, kt & 1, (kt + 2) * 32, tid);
        CP_COMMIT();
    }

    const float oscale = (mode == 2) ? 0.125f : 1.0f;
#pragma unroll
    for (int mf = 0; mf < 4; mf++) {
        const int m0 = rowBase + wm * 64 + mf * 16 + r0;
        const int m1 = m0 + 8;
#pragma unroll
        for (int nf = 0; nf < 4; nf++) {
            const int n = colBase + wn * 32 + nf * 8 + 2 * c0;
            float2 v0, v1;
            v0.x = acc[mf][nf][0] + bias[n];
            v0.y = acc[mf][nf][1] + bias[n + 1];
            v1.x = acc[mf][nf][2] + bias[n];
            v1.y = acc[mf][nf][3] + bias[n + 1];
            if (mode == 1) {
                *(float2*)(C + (size_t)m0 * DMODEL + n) = v0;
                *(float2*)(C + (size_t)m1 * DMODEL + n) = v1;
            } else {
                v0.x = __uint_as_float(f2tf(v0.x * oscale));
                v0.y = __uint_as_float(f2tf(v0.y * oscale));
                v1.x = __uint_as_float(f2tf(v1.x * oscale));
                v1.y = __uint_as_float(f2tf(v1.y * oscale));
                const int hh = n >> 6, dd = n & 63;
                const int b0 = m0 >> 11, s0 = m0 & (SEQ - 1);
                const int b1 = m1 >> 11, s1 = m1 & (SEQ - 1);
                *(float2*)(C + ((((size_t)b0 * H_HEADS + hh) * SEQ + s0) << 6) + dd) = v0;
                *(float2*)(C + ((((size_t)b1 * H_HEADS + hh) * SEQ + s1) << 6) + dd) = v1;
            }
        }
    }
}

// ============================================================================
// Flash attention, tf32 mma.sync, crossbar-optimized:
//   q-tile 128, 4 warps, warp owns 32 q rows (2 m-frags) -> K/V fragments
//   reused 2x. Q fragments live in registers (loaded once from gmem).
//   P converted S-cfrag -> PV-afrag via quad shuffles (no smem round trip).
//   K/V/mask double-buffered via cp.async.
// ============================================================================
#define QST 68
#define VST 72
// Ks[2][64][QST] + Vs[2][64][VST] + Ms[2][64]
#define ATT_SMEM ((2 * 64 * QST + 2 * 64 * VST) * 4 + 2 * 64 * 4)   // 72192 B

__device__ __forceinline__ void attn_fill(uint32_t kb, uint32_t vb, uint32_t mb,
                                          const float* __restrict__ Kg,
                                          const float* __restrict__ Vg,
                                          const int* __restrict__ mg,
                                          int kt, int tid)
{
#pragma unroll
    for (int i = 0; i < 8; i++) {
        int idx = tid + 128 * i;
        int r = idx >> 4, d4 = (idx & 15) << 2;
        CP_ASYNC16(kb + (uint32_t)((r * QST + d4) * 4),
                   Kg + ((size_t)kt * 64 + r) * 64 + d4);
        CP_ASYNC16(vb + (uint32_t)((r * VST + d4) * 4),
                   Vg + ((size_t)kt * 64 + r) * 64 + d4);
    }
    if (tid < 64) CP_ASYNC4(mb + (uint32_t)(tid * 4), mg + kt * 64 + tid);
}

__global__ __launch_bounds__(128, 2)
void attn_mma(const float* __restrict__ Q, const float* __restrict__ Kg_,
              const float* __restrict__ Vg_, const int* __restrict__ mask,
              float* __restrict__ ctx)
{
    extern __shared__ float sm[];
    float* Ks = sm;                               // [2][64][QST]
    float* Vs = sm + 2 * 64 * QST;                // [2][64][VST]
    int*   Ms = (int*)(sm + 2 * 64 * QST + 2 * 64 * VST);  // [2][64]

    const uint32_t sb  = smem_u32(sm);
    const uint32_t KsB = sb;
    const uint32_t VsB = sb + 2 * 64 * QST * 4;
    const uint32_t MsB = sb + (2 * 64 * QST + 2 * 64 * VST) * 4;

    const int tid  = threadIdx.x;
    const int lane = tid & 31, wid = tid >> 5;
    const int r0 = lane >> 2, c0 = lane & 3;
    const int qt = blockIdx.x, h = blockIdx.y, b = blockIdx.z;

    const size_t bh = (size_t)b * H_HEADS + h;
    const float* Qg = Q   + (bh * SEQ + (size_t)qt * 128) * 64;
    const float* Kg = Kg_ + bh * SEQ * 64;
    const float* Vg = Vg_ + bh * SEQ * 64;
    const int*   mg = mask + (size_t)b * SEQ;

    // ---- Q fragments: registers for the whole kernel (Q is tf32-pre-rounded,
    //      pre-scaled by 1/8). Warp owns 32 q rows: mf in {0,1} -> +0/+16.
    uint32_t qa[2][8][4];
    {
        const float* Qw = Qg + (size_t)(wid * 32) * 64;
#pragma unroll
        for (int mf = 0; mf < 2; mf++)
#pragma unroll
            for (int ks = 0; ks < 8; ks++) {
                const int kc = ks * 8;
                const float* p = Qw + (size_t)(mf * 16 + r0) * 64 + kc + c0;
                qa[mf][ks][0] = __float_as_uint(p[0]);
                qa[mf][ks][1] = __float_as_uint(p[8 * 64]);
                qa[mf][ks][2] = __float_as_uint(p[4]);
                qa[mf][ks][3] = __float_as_uint(p[8 * 64 + 4]);
            }
    }

    float o[2][8][4];
#pragma unroll
    for (int mf = 0; mf < 2; mf++)
#pragma unroll
        for (int df = 0; df < 8; df++)
#pragma unroll
            for (int r = 0; r < 4; r++) o[mf][df][r] = 0.f;

    float mprev[2][2], lsum[2][2];
#pragma unroll
    for (int mf = 0; mf < 2; mf++) {
        mprev[mf][0] = -1e30f; mprev[mf][1] = -1e30f;
        lsum[mf][0] = 0.f;     lsum[mf][1] = 0.f;
    }

    // shuffle source lanes for S-cfrag -> PV-afrag conversion
    const int Lq  = (lane & 28) | (c0 >> 1);
    const int Lq2 = Lq | 2;
    const bool oddc = (c0 & 1) != 0;

    attn_fill(KsB, VsB, MsB, Kg, Vg, mg, 0, tid);
    CP_COMMIT();

    const int nkt = SEQ / 64;
    for (int kt = 0; kt < nkt; kt++) {
        CP_WAIT0();
        __syncthreads();

        const int cur = kt & 1;
        if (kt + 1 < nkt) {
            const int nxt = (kt + 1) & 1;
            attn_fill(KsB + (uint32_t)(nxt * 64 * QST * 4),
                      VsB + (uint32_t)(nxt * 64 * VST * 4),
                      MsB + (uint32_t)(nxt * 256),
                      Kg, Vg, mg, kt + 1, tid);
        }
        CP_COMMIT();

        const float* ks_ = Ks + cur * 64 * QST;
        const float* vs_ = Vs + cur * 64 * VST;
        const int*   ms_ = Ms + cur * 64;

        // -------- S = Q . K^T : K fragment loaded once, used by both mf ----
        float s[2][8][4];
#pragma unroll
        for (int mf = 0; mf < 2; mf++)
#pragma unroll
            for (int nf = 0; nf < 8; nf++)
#pragma unroll
                for (int r = 0; r < 4; r++) s[mf][nf][r] = 0.f;

#pragma unroll
        for (int ks = 0; ks < 8; ks++) {
            const int kc = ks * 8;
#pragma unroll
            for (int nf = 0; nf < 8; nf++) {
                uint32_t bb[2];
                const float* bp = ks_ + (nf * 8 + r0) * QST + kc + c0;
                bb[0] = __float_as_uint(bp[0]);
                bb[1] = __float_as_uint(bp[4]);
                mma_tf32(s[0][nf], qa[0][ks], bb);
                mma_tf32(s[1][nf], qa[1][ks], bb);
            }
        }

        // -------- mask --------
#pragma unroll
        for (int nf = 0; nf < 8; nf++) {
            const int nc = nf * 8 + 2 * c0;
            const bool k0m = ms_[nc] != 0, k1m = ms_[nc + 1] != 0;
#pragma unroll
            for (int mf = 0; mf < 2; mf++) {
                s[mf][nf][0] = k0m ? s[mf][nf][0] : -1e9f;
                s[mf][nf][1] = k1m ? s[mf][nf][1] : -1e9f;
                s[mf][nf][2] = k0m ? s[mf][nf][2] : -1e9f;
                s[mf][nf][3] = k1m ? s[mf][nf][3] : -1e9f;
            }
        }

        // -------- online softmax (per mf; rows r0 and r0+8) --------
#pragma unroll
        for (int mf = 0; mf < 2; mf++) {
            float rmax0 = -1e30f, rmax1 = -1e30f;
#pragma unroll
            for (int nf = 0; nf < 8; nf++) {
                rmax0 = fmaxf(rmax0, fmaxf(s[mf][nf][0], s[mf][nf][1]));
                rmax1 = fmaxf(rmax1, fmaxf(s[mf][nf][2], s[mf][nf][3]));
            }
            rmax0 = fmaxf(rmax0, __shfl_xor_sync(0xffffffffu, rmax0, 1));
            rmax0 = fmaxf(rmax0, __shfl_xor_sync(0xffffffffu, rmax0, 2));
            rmax1 = fmaxf(rmax1, __shfl_xor_sync(0xffffffffu, rmax1, 1));
            rmax1 = fmaxf(rmax1, __shfl_xor_sync(0xffffffffu, rmax1, 2));

            const float mn0 = fmaxf(mprev[mf][0], rmax0);
            const float mn1 = fmaxf(mprev[mf][1], rmax1);
            const float fac0 = __expf(mprev[mf][0] - mn0);
            const float fac1 = __expf(mprev[mf][1] - mn1);

            float rs0 = 0.f, rs1 = 0.f;
#pragma unroll
            for (int nf = 0; nf < 8; nf++) {
                s[mf][nf][0] = __expf(s[mf][nf][0] - mn0);
                s[mf][nf][1] = __expf(s[mf][nf][1] - mn0);
                s[mf][nf][2] = __expf(s[mf][nf][2] - mn1);
                s[mf][nf][3] = __expf(s[mf][nf][3] - mn1);
                rs0 += s[mf][nf][0] + s[mf][nf][1];
                rs1 += s[mf][nf][2] + s[mf][nf][3];
            }
            rs0 += __shfl_xor_sync(0xffffffffu, rs0, 1);
            rs0 += __shfl_xor_sync(0xffffffffu, rs0, 2);
            rs1 += __shfl_xor_sync(0xffffffffu, rs1, 1);
            rs1 += __shfl_xor_sync(0xffffffffu, rs1, 2);

            lsum[mf][0] = lsum[mf][0] * fac0 + rs0;
            lsum[mf][1] = lsum[mf][1] * fac1 + rs1;
            mprev[mf][0] = mn0; mprev[mf][1] = mn1;
#pragma unroll
            for (int df = 0; df < 8; df++) {
                o[mf][df][0] *= fac0; o[mf][df][1] *= fac0;
                o[mf][df][2] *= fac1; o[mf][df][3] *= fac1;
            }
        }

        // -------- O += P . V : P a-frags built via quad shuffles ----------
#pragma unroll
        for (int ks = 0; ks < 8; ks++) {
            const int kc = ks * 8;
            uint32_t a0[4], a1[4];
#pragma unroll
            for (int mf = 0; mf < 2; mf++) {
                float t0 = __shfl_sync(0xffffffffu, s[mf][ks][0], Lq);
                float t1 = __shfl_sync(0xffffffffu, s[mf][ks][1], Lq);
                float t2 = __shfl_sync(0xffffffffu, s[mf][ks][2], Lq);
                float t3 = __shfl_sync(0xffffffffu, s[mf][ks][3], Lq);
                float u0 = __shfl_sync(0xffffffffu, s[mf][ks][0], Lq2);
                float u1 = __shfl_sync(0xffffffffu, s[mf][ks][1], Lq2);
                float u2 = __shfl_sync(0xffffffffu, s[mf][ks][2], Lq2);
                float u3 = __shfl_sync(0xffffffffu, s[mf][ks][3], Lq2);
                uint32_t* a = mf ? a1 : a0;
                a[0] = f2tf(oddc ? t1 : t0);
                a[1] = f2tf(oddc ? t3 : t2);
                a[2] = f2tf(oddc ? u1 : u0);
                a[3] = f2tf(oddc ? u3 : u2);
            }
#pragma unroll
            for (int df = 0; df < 8; df++) {
                uint32_t bb[2];
                const float* vp = vs_ + (kc + c0) * VST + df * 8 + r0;
                bb[0] = __float_as_uint(vp[0]);
                bb[1] = __float_as_uint(vp[4 * VST]);
                mma_tf32(o[0][df], a0, bb);
                mma_tf32(o[1][df], a1, bb);
            }
        }
    }

    // -------- finalize: ctx (B,S,H,64) --------
#pragma unroll
    for (int mf = 0; mf < 2; mf++) {
        const float inv0 = (lsum[mf][0] > 0.f) ? (1.f / lsum[mf][0]) : 0.f;
        const float inv1 = (lsum[mf][1] > 0.f) ? (1.f / lsum[mf][1]) : 0.f;
        const int q0 = qt * 128 + wid * 32 + mf * 16 + r0;
#pragma unroll
        for (int df = 0; df < 8; df++) {
            const int d = df * 8 + 2 * c0;
            float2 v0 = {o[mf][df][0] * inv0, o[mf][df][1] * inv0};
            float2 v1 = {o[mf][df][2] * inv1, o[mf][df][3] * inv1};
            *(float2*)(ctx + ((size_t)(b * SEQ + q0) * H_HEADS + h) * 64 + d) = v0;
            *(float2*)(ctx + ((size_t)(b * SEQ + q0 + 8) * H_HEADS + h) * 64 + d) = v1;
        }
    }
}

// ============================================================================
// launch
// ============================================================================
extern "C" void kernel_launch(void* const* d_in, const int* in_sizes, int n_in,
                              void* d_out, int out_size)
{
    const float* query = (const float*)d_in[0];
    const float* key_  = (const float*)d_in[1];
    const float* value = (const float*)d_in[2];
    const int*   mask  = (const int*)  d_in[3];
    const float* Wq = (const float*)d_in[4];
    const float* bq = (const float*)d_in[5];
    const float* Wk = (const float*)d_in[6];
    const float* bk = (const float*)d_in[7];
    const float* Wv = (const float*)d_in[8];
    const float* bv = (const float*)d_in[9];
    const float* Wo = (const float*)d_in[10];
    const float* bo = (const float*)d_in[11];
    float* out = (float*)d_out;

    float *gq, *gk, *gv, *gctx;
    cudaGetSymbolAddress((void**)&gq,  g_q);
    cudaGetSymbolAddress((void**)&gk,  g_k);
    cudaGetSymbolAddress((void**)&gv,  g_v);
    cudaGetSymbolAddress((void**)&gctx, g_ctx);

    cudaFuncSetAttribute(gemm_mma,
                         cudaFuncAttributeMaxDynamicSharedMemorySize, GEMM_SMEM);
    cudaFuncSetAttribute(attn_mma,
                         cudaFuncAttributeMaxDynamicSharedMemorySize, ATT_SMEM);

    const int M = BATCH * SEQ;                 // 8192
    dim3 ggrid(DMODEL / 128, M / 128);         // (8, 64)
    dim3 gblock(256);

    gemm_mma<<<ggrid, gblock, GEMM_SMEM>>>(query, Wq, bq, gq, 2);  // Q: tf32 + 1/8
    gemm_mma<<<ggrid, gblock, GEMM_SMEM>>>(key_,  Wk, bk, gk, 0);  // K: tf32
    gemm_mma<<<ggrid, gblock, GEMM_SMEM>>>(value, Wv, bv, gv, 0);  // V: tf32

    dim3 agrid(SEQ / 128, H_HEADS, BATCH);     // (16, 16, 4)
    attn_mma<<<agrid, dim3(128), ATT_SMEM>>>(gq, gk, gv, mask, gctx);

    gemm_mma<<<ggrid, gblock, GEMM_SMEM>>>(gctx, Wo, bo, out, 1);
}

// round 6
// speedup vs baseline: 3.8483x; 1.0413x over previous
#include <cuda_runtime.h>
#include <cstdint>

// ---------------- problem constants ----------------
#define H_HEADS 16
#define DMODEL  1024
#define BATCH   4
#define SEQ     2048
#define MTOT    (BATCH * SEQ)          // 8192

// ---------------- scratch (static device globals; no allocs) ----------------
__device__ float g_q[(size_t)BATCH * H_HEADS * SEQ * 64];   // tf32, pre-scaled 0.125*log2e
__device__ float g_k[(size_t)BATCH * H_HEADS * SEQ * 64];   // tf32
__device__ float g_v[(size_t)BATCH * H_HEADS * SEQ * 64];   // tf32
__device__ float g_ctx[(size_t)BATCH * SEQ * DMODEL];       // tf32-rounded (B,S,H*dk)
__device__ float g_ain[3][(size_t)MTOT * DMODEL];           // tf32 copies of q/k/v inputs
__device__ float g_win[4][(size_t)DMODEL * DMODEL];         // tf32 copies of Wq/Wk/Wv/Wo

// ---------------- helpers ----------------
__device__ __forceinline__ uint32_t smem_u32(const void* p) {
    uint32_t a;
    asm("{ .reg .u64 t; cvta.to.shared.u64 t, %1; cvt.u32.u64 %0, t; }"
        : "=r"(a) : "l"(p));
    return a;
}

__device__ __forceinline__ uint32_t f2tf(float x) {
    uint32_t r;
    asm("cvt.rna.tf32.f32 %0, %1;" : "=r"(r) : "f"(x));
    return r;
}

__device__ __forceinline__ float ex2(float x) {
    float y;
    asm("ex2.approx.f32 %0, %1;" : "=f"(y) : "f"(x));
    return y;
}

// D += A(m16k8, tf32) * B(k8n8, tf32)   (row.col)
__device__ __forceinline__ void mma_tf32(float* c, const uint32_t* a, const uint32_t* b) {
    asm volatile(
        "mma.sync.aligned.m16n8k8.row.col.f32.tf32.tf32.f32 "
        "{%0,%1,%2,%3},{%4,%5,%6,%7},{%8,%9},{%0,%1,%2,%3};"
        : "+f"(c[0]), "+f"(c[1]), "+f"(c[2]), "+f"(c[3])
        : "r"(a[0]), "r"(a[1]), "r"(a[2]), "r"(a[3]), "r"(b[0]), "r"(b[1]));
}

#define CP_ASYNC16(dst, src) \
    asm volatile("cp.async.cg.shared.global [%0], [%1], 16;" :: "r"(dst), "l"(src) : "memory")
#define CP_ASYNC4(dst, src) \
    asm volatile("cp.async.ca.shared.global [%0], [%1], 4;" :: "r"(dst), "l"(src) : "memory")
#define CP_COMMIT() asm volatile("cp.async.commit_group;" ::: "memory")
#define CP_WAIT1()  asm volatile("cp.async.wait_group 1;" ::: "memory")
#define CP_WAIT0()  asm volatile("cp.async.wait_group 0;" ::: "memory")

// ============================================================================
// elementwise tf32 rounding prepass (n % 4 == 0)
// ============================================================================
__global__ __launch_bounds__(256)
void round_tf32_kernel(const float* __restrict__ src, float* __restrict__ dst, int n)
{
    int i = (blockIdx.x * 256 + threadIdx.x) * 4;
    if (i < n) {
        float4 v = *(const float4*)(src + i);
        v.x = __uint_as_float(f2tf(v.x));
        v.y = __uint_as_float(f2tf(v.y));
        v.z = __uint_as_float(f2tf(v.z));
        v.w = __uint_as_float(f2tf(v.w));
        *(float4*)(dst + i) = v;
    }
}

// ============================================================================
// tf32 mma.sync GEMM-NT, inputs PRE-ROUNDED to tf32 (no cvt in hot loop):
//   C[m,n] = sum_k A[m,k] * W[n,k] + bias[n]
//   mode 0: head-split out, tf32-rounded            (K, V)
//   mode 2: head-split out, tf32-rounded, x scaleQ  (Q)
//   mode 1: plain row-major out, full fp32          (final output)
// ============================================================================
#define GS 36
#define GEMM_SMEM (2 * 2 * 128 * GS * 4)        // 73728 B
#define QSCALE (0.125f * 1.4426950408889634f)   // 1/sqrt(dk) * log2(e)

__device__ __forceinline__ void gemm_load_stage(uint32_t sbase, uint32_t woffB,
                                                const float* __restrict__ Ag,
                                                const float* __restrict__ Wg,
                                                int s, int k0, int tid)
{
#pragma unroll
    for (int i = 0; i < 4; i++) {
        int idx = tid + 256 * i;
        int r   = idx >> 3;
        int c4  = (idx & 7) << 2;
        uint32_t d = (uint32_t)(((s * 128 + r) * GS + c4) * 4);
        CP_ASYNC16(sbase + d,         Ag + (size_t)r * DMODEL + k0 + c4);
        CP_ASYNC16(sbase + woffB + d, Wg + (size_t)r * DMODEL + k0 + c4);
    }
}

__global__ __launch_bounds__(256)
void gemm_mma(const float* __restrict__ A, const float* __restrict__ W,
              const float* __restrict__ bias, float* __restrict__ C, int mode)
{
    extern __shared__ float sm[];
    const float* As  = sm;
    const float* Ws_ = sm + 2 * 128 * GS;
    const uint32_t sbase = smem_u32(sm);
    const uint32_t woffB = (uint32_t)(2 * 128 * GS * 4);

    const int tid  = threadIdx.x;
    const int lane = tid & 31, wid = tid >> 5;
    const int wm = wid >> 2, wn = wid & 3;
    const int r0 = lane >> 2, c0 = lane & 3;

    const int rowBase = blockIdx.y * 128;
    const int colBase = blockIdx.x * 128;
    const float* Ag = A + (size_t)rowBase * DMODEL;
    const float* Wg = W + (size_t)colBase * DMODEL;

    float acc[4][4][4];
#pragma unroll
    for (int mf = 0; mf < 4; mf++)
#pragma unroll
        for (int nf = 0; nf < 4; nf++)
#pragma unroll
            for (int r = 0; r < 4; r++) acc[mf][nf][r] = 0.f;

    gemm_load_stage(sbase, woffB, Ag, Wg, 0, 0, tid);  CP_COMMIT();
    gemm_load_stage(sbase, woffB, Ag, Wg, 1, 32, tid); CP_COMMIT();

    for (int kt = 0; kt < DMODEL / 32; kt++) {
        CP_WAIT1();
        __syncthreads();
        const float* as = As  + (kt & 1) * 128 * GS;
        const float* ws = Ws_ + (kt & 1) * 128 * GS;
#pragma unroll
        for (int ks = 0; ks < 4; ks++) {
            const int kc = ks * 8;
            uint32_t af[4][4], bf[4][2];
#pragma unroll
            for (int mf = 0; mf < 4; mf++) {
                const float* ap = as + (wm * 64 + mf * 16 + r0) * GS + kc + c0;
                af[mf][0] = __float_as_uint(ap[0]);
                af[mf][1] = __float_as_uint(ap[8 * GS]);
                af[mf][2] = __float_as_uint(ap[4]);
                af[mf][3] = __float_as_uint(ap[8 * GS + 4]);
            }
#pragma unroll
            for (int nf = 0; nf < 4; nf++) {
                const float* wp = ws + (wn * 32 + nf * 8 + r0) * GS + kc + c0;
                bf[nf][0] = __float_as_uint(wp[0]);
                bf[nf][1] = __float_as_uint(wp[4]);
            }
#pragma unroll
            for (int mf = 0; mf < 4; mf++)
#pragma unroll
                for (int nf = 0; nf < 4; nf++)
                    mma_tf32(acc[mf][nf], af[mf], bf[nf]);
        }
        __syncthreads();
        if (kt + 2 < DMODEL / 32)
            gemm_load_stage(sbase, woffB, Ag, Wg, kt & 1, (kt + 2) * 32, tid);
        CP_COMMIT();
    }

    const float oscale = (mode == 2) ? QSCALE : 1.0f;
#pragma unroll
    for (int mf = 0; mf < 4; mf++) {
        const int m0 = rowBase + wm * 64 + mf * 16 + r0;
        const int m1 = m0 + 8;
#pragma unroll
        for (int nf = 0; nf < 4; nf++) {
            const int n = colBase + wn * 32 + nf * 8 + 2 * c0;
            float2 v0, v1;
            v0.x = acc[mf][nf][0] + bias[n];
            v0.y = acc[mf][nf][1] + bias[n + 1];
            v1.x = acc[mf][nf][2] + bias[n];
            v1.y = acc[mf][nf][3] + bias[n + 1];
            if (mode == 1) {
                *(float2*)(C + (size_t)m0 * DMODEL + n) = v0;
                *(float2*)(C + (size_t)m1 * DMODEL + n) = v1;
            } else {
                v0.x = __uint_as_float(f2tf(v0.x * oscale));
                v0.y = __uint_as_float(f2tf(v0.y * oscale));
                v1.x = __uint_as_float(f2tf(v1.x * oscale));
                v1.y = __uint_as_float(f2tf(v1.y * oscale));
                const int hh = n >> 6, dd = n & 63;
                const int b0 = m0 >> 11, s0 = m0 & (SEQ - 1);
                const int b1 = m1 >> 11, s1 = m1 & (SEQ - 1);
                *(float2*)(C + ((((size_t)b0 * H_HEADS + hh) * SEQ + s0) << 6) + dd) = v0;
                *(float2*)(C + ((((size_t)b1 * H_HEADS + hh) * SEQ + s1) << 6) + dd) = v1;
            }
        }
    }
}

// ============================================================================
// Flash attention, tf32 mma.sync, exp2-domain softmax:
//   q-tile 128, 4 warps, warp owns 32 q rows (2 m-frags); Q frags in regs;
//   P via quad shuffles; K/V/mask double-buffered cp.async.
//   Scores arrive pre-scaled by 1/8*log2e -> softmax uses raw ex2.approx.
// ============================================================================
#define QST 68
#define VST 72
#define ATT_SMEM ((2 * 64 * QST + 2 * 64 * VST) * 4 + 2 * 64 * 4)   // 72192 B

__device__ __forceinline__ void attn_fill(uint32_t kb, uint32_t vb, uint32_t mb,
                                          const float* __restrict__ Kg,
                                          const float* __restrict__ Vg,
                                          const int* __restrict__ mg,
                                          int kt, int tid)
{
#pragma unroll
    for (int i = 0; i < 8; i++) {
        int idx = tid + 128 * i;
        int r = idx >> 4, d4 = (idx & 15) << 2;
        CP_ASYNC16(kb + (uint32_t)((r * QST + d4) * 4),
                   Kg + ((size_t)kt * 64 + r) * 64 + d4);
        CP_ASYNC16(vb + (uint32_t)((r * VST + d4) * 4),
                   Vg + ((size_t)kt * 64 + r) * 64 + d4);
    }
    if (tid < 64) CP_ASYNC4(mb + (uint32_t)(tid * 4), mg + kt * 64 + tid);
}

__global__ __launch_bounds__(128, 2)
void attn_mma(const float* __restrict__ Q, const float* __restrict__ Kg_,
              const float* __restrict__ Vg_, const int* __restrict__ mask,
              float* __restrict__ ctx)
{
    extern __shared__ float sm[];
    float* Ks = sm;                               // [2][64][QST]
    float* Vs = sm + 2 * 64 * QST;                // [2][64][VST]
    int*   Ms = (int*)(sm + 2 * 64 * QST + 2 * 64 * VST);  // [2][64]

    const uint32_t sb  = smem_u32(sm);
    const uint32_t KsB = sb;
    const uint32_t VsB = sb + 2 * 64 * QST * 4;
    const uint32_t MsB = sb + (2 * 64 * QST + 2 * 64 * VST) * 4;

    const int tid  = threadIdx.x;
    const int lane = tid & 31, wid = tid >> 5;
    const int r0 = lane >> 2, c0 = lane & 3;
    const int qt = blockIdx.x, h = blockIdx.y, b = blockIdx.z;

    const size_t bh = (size_t)b * H_HEADS + h;
    const float* Qg = Q   + (bh * SEQ + (size_t)qt * 128) * 64;
    const float* Kg = Kg_ + bh * SEQ * 64;
    const float* Vg = Vg_ + bh * SEQ * 64;
    const int*   mg = mask + (size_t)b * SEQ;

    // Q fragments in registers for the whole kernel
    uint32_t qa[2][8][4];
    {
        const float* Qw = Qg + (size_t)(wid * 32) * 64;
#pragma unroll
        for (int mf = 0; mf < 2; mf++)
#pragma unroll
            for (int ks = 0; ks < 8; ks++) {
                const int kc = ks * 8;
                const float* p = Qw + (size_t)(mf * 16 + r0) * 64 + kc + c0;
                qa[mf][ks][0] = __float_as_uint(p[0]);
                qa[mf][ks][1] = __float_as_uint(p[8 * 64]);
                qa[mf][ks][2] = __float_as_uint(p[4]);
                qa[mf][ks][3] = __float_as_uint(p[8 * 64 + 4]);
            }
    }

    float o[2][8][4];
#pragma unroll
    for (int mf = 0; mf < 2; mf++)
#pragma unroll
        for (int df = 0; df < 8; df++)
#pragma unroll
            for (int r = 0; r < 4; r++) o[mf][df][r] = 0.f;

    float mprev[2][2], lsum[2][2];
#pragma unroll
    for (int mf = 0; mf < 2; mf++) {
        mprev[mf][0] = -1e30f; mprev[mf][1] = -1e30f;
        lsum[mf][0] = 0.f;     lsum[mf][1] = 0.f;
    }

    const int Lq  = (lane & 28) | (c0 >> 1);
    const int Lq2 = Lq | 2;
    const bool oddc = (c0 & 1) != 0;

    attn_fill(KsB, VsB, MsB, Kg, Vg, mg, 0, tid);
    CP_COMMIT();

    const int nkt = SEQ / 64;
    for (int kt = 0; kt < nkt; kt++) {
        CP_WAIT0();
        __syncthreads();

        const int cur = kt & 1;
        if (kt + 1 < nkt) {
            const int nxt = (kt + 1) & 1;
            attn_fill(KsB + (uint32_t)(nxt * 64 * QST * 4),
                      VsB + (uint32_t)(nxt * 64 * VST * 4),
                      MsB + (uint32_t)(nxt * 256),
                      Kg, Vg, mg, kt + 1, tid);
        }
        CP_COMMIT();

        const float* ks_ = Ks + cur * 64 * QST;
        const float* vs_ = Vs + cur * 64 * VST;
        const int*   ms_ = Ms + cur * 64;

        // -------- S = Q . K^T (log2-domain scores) --------
        float s[2][8][4];
#pragma unroll
        for (int mf = 0; mf < 2; mf++)
#pragma unroll
            for (int nf = 0; nf < 8; nf++)
#pragma unroll
                for (int r = 0; r < 4; r++) s[mf][nf][r] = 0.f;

#pragma unroll
        for (int ks = 0; ks < 8; ks++) {
            const int kc = ks * 8;
#pragma unroll
            for (int nf = 0; nf < 8; nf++) {
                uint32_t bb[2];
                const float* bp = ks_ + (nf * 8 + r0) * QST + kc + c0;
                bb[0] = __float_as_uint(bp[0]);
                bb[1] = __float_as_uint(bp[4]);
                mma_tf32(s[0][nf], qa[0][ks], bb);
                mma_tf32(s[1][nf], qa[1][ks], bb);
            }
        }

        // -------- mask --------
#pragma unroll
        for (int nf = 0; nf < 8; nf++) {
            const int nc = nf * 8 + 2 * c0;
            const bool k0m = ms_[nc] != 0, k1m = ms_[nc + 1] != 0;
#pragma unroll
            for (int mf = 0; mf < 2; mf++) {
                s[mf][nf][0] = k0m ? s[mf][nf][0] : -1e9f;
                s[mf][nf][1] = k1m ? s[mf][nf][1] : -1e9f;
                s[mf][nf][2] = k0m ? s[mf][nf][2] : -1e9f;
                s[mf][nf][3] = k1m ? s[mf][nf][3] : -1e9f;
            }
        }

        // -------- online softmax in exp2 domain --------
#pragma unroll
        for (int mf = 0; mf < 2; mf++) {
            float rmax0 = -1e30f, rmax1 = -1e30f;
#pragma unroll
            for (int nf = 0; nf < 8; nf++) {
                rmax0 = fmaxf(rmax0, fmaxf(s[mf][nf][0], s[mf][nf][1]));
                rmax1 = fmaxf(rmax1, fmaxf(s[mf][nf][2], s[mf][nf][3]));
            }
            rmax0 = fmaxf(rmax0, __shfl_xor_sync(0xffffffffu, rmax0, 1));
            rmax0 = fmaxf(rmax0, __shfl_xor_sync(0xffffffffu, rmax0, 2));
            rmax1 = fmaxf(rmax1, __shfl_xor_sync(0xffffffffu, rmax1, 1));
            rmax1 = fmaxf(rmax1, __shfl_xor_sync(0xffffffffu, rmax1, 2));

            const float mn0 = fmaxf(mprev[mf][0], rmax0);
            const float mn1 = fmaxf(mprev[mf][1], rmax1);
            const float fac0 = ex2(mprev[mf][0] - mn0);
            const float fac1 = ex2(mprev[mf][1] - mn1);

            float rs0 = 0.f, rs1 = 0.f;
#pragma unroll
            for (int nf = 0; nf < 8; nf++) {
                s[mf][nf][0] = ex2(s[mf][nf][0] - mn0);
                s[mf][nf][1] = ex2(s[mf][nf][1] - mn0);
                s[mf][nf][2] = ex2(s[mf][nf][2] - mn1);
                s[mf][nf][3] = ex2(s[mf][nf][3] - mn1);
                rs0 += s[mf][nf][0] + s[mf][nf][1];
                rs1 += s[mf][nf][2] + s[mf][nf][3];
            }
            rs0 += __shfl_xor_sync(0xffffffffu, rs0, 1);
            rs0 += __shfl_xor_sync(0xffffffffu, rs0, 2);
            rs1 += __shfl_xor_sync(0xffffffffu, rs1, 1);
            rs1 += __shfl_xor_sync(0xffffffffu, rs1, 2);

            lsum[mf][0] = lsum[mf][0] * fac0 + rs0;
            lsum[mf][1] = lsum[mf][1] * fac1 + rs1;
            mprev[mf][0] = mn0; mprev[mf][1] = mn1;
#pragma unroll
            for (int df = 0; df < 8; df++) {
                o[mf][df][0] *= fac0; o[mf][df][1] *= fac0;
                o[mf][df][2] *= fac1; o[mf][df][3] *= fac1;
            }
        }

        // -------- O += P . V (P a-frags via quad shuffles) --------
#pragma unroll
        for (int ks = 0; ks < 8; ks++) {
            const int kc = ks * 8;
            uint32_t a0[4], a1[4];
#pragma unroll
            for (int mf = 0; mf < 2; mf++) {
                float t0 = __shfl_sync(0xffffffffu, s[mf][ks][0], Lq);
                float t1 = __shfl_sync(0xffffffffu, s[mf][ks][1], Lq);
                float t2 = __shfl_sync(0xffffffffu, s[mf][ks][2], Lq);
                float t3 = __shfl_sync(0xffffffffu, s[mf][ks][3], Lq);
                float u0 = __shfl_sync(0xffffffffu, s[mf][ks][0], Lq2);
                float u1 = __shfl_sync(0xffffffffu, s[mf][ks][1], Lq2);
                float u2 = __shfl_sync(0xffffffffu, s[mf][ks][2], Lq2);
                float u3 = __shfl_sync(0xffffffffu, s[mf][ks][3], Lq2);
                uint32_t* a = mf ? a1 : a0;
                a[0] = f2tf(oddc ? t1 : t0);
                a[1] = f2tf(oddc ? t3 : t2);
                a[2] = f2tf(oddc ? u1 : u0);
                a[3] = f2tf(oddc ? u3 : u2);
            }
#pragma unroll
            for (int df = 0; df < 8; df++) {
                uint32_t bb[2];
                const float* vp = vs_ + (kc + c0) * VST + df * 8 + r0;
                bb[0] = __float_as_uint(vp[0]);
                bb[1] = __float_as_uint(vp[4 * VST]);
                mma_tf32(o[0][df], a0, bb);
                mma_tf32(o[1][df], a1, bb);
            }
        }
    }

    // -------- finalize: ctx (B,S,H,64), tf32-rounded for the Wo GEMM --------
#pragma unroll
    for (int mf = 0; mf < 2; mf++) {
        const float inv0 = (lsum[mf][0] > 0.f) ? (1.f / lsum[mf][0]) : 0.f;
        const float inv1 = (lsum[mf][1] > 0.f) ? (1.f / lsum[mf][1]) : 0.f;
        const int q0 = qt * 128 + wid * 32 + mf * 16 + r0;
#pragma unroll
        for (int df = 0; df < 8; df++) {
            const int d = df * 8 + 2 * c0;
            float2 v0, v1;
            v0.x = __uint_as_float(f2tf(o[mf][df][0] * inv0));
            v0.y = __uint_as_float(f2tf(o[mf][df][1] * inv0));
            v1.x = __uint_as_float(f2tf(o[mf][df][2] * inv1));
            v1.y = __uint_as_float(f2tf(o[mf][df][3] * inv1));
            *(float2*)(ctx + ((size_t)(b * SEQ + q0) * H_HEADS + h) * 64 + d) = v0;
            *(float2*)(ctx + ((size_t)(b * SEQ + q0 + 8) * H_HEADS + h) * 64 + d) = v1;
        }
    }
}

// ============================================================================
// launch
// ============================================================================
extern "C" void kernel_launch(void* const* d_in, const int* in_sizes, int n_in,
                              void* d_out, int out_size)
{
    const float* query = (const float*)d_in[0];
    const float* key_  = (const float*)d_in[1];
    const float* value = (const float*)d_in[2];
    const int*   mask  = (const int*)  d_in[3];
    const float* Wq = (const float*)d_in[4];
    const float* bq = (const float*)d_in[5];
    const float* Wk = (const float*)d_in[6];
    const float* bk = (const float*)d_in[7];
    const float* Wv = (const float*)d_in[8];
    const float* bv = (const float*)d_in[9];
    const float* Wo = (const float*)d_in[10];
    const float* bo = (const float*)d_in[11];
    float* out = (float*)d_out;

    float *gq, *gk, *gv, *gctx, *gain, *gwin;
    cudaGetSymbolAddress((void**)&gq,   g_q);
    cudaGetSymbolAddress((void**)&gk,   g_k);
    cudaGetSymbolAddress((void**)&gv,   g_v);
    cudaGetSymbolAddress((void**)&gctx, g_ctx);
    cudaGetSymbolAddress((void**)&gain, g_ain);
    cudaGetSymbolAddress((void**)&gwin, g_win);

    float* aq = gain;
    float* ak = gain + (size_t)MTOT * DMODEL;
    float* av = gain + 2 * (size_t)MTOT * DMODEL;
    float* wq = gwin;
    float* wk = gwin + (size_t)DMODEL * DMODEL;
    float* wv = gwin + 2 * (size_t)DMODEL * DMODEL;
    float* wo = gwin + 3 * (size_t)DMODEL * DMODEL;

    cudaFuncSetAttribute(gemm_mma,
                         cudaFuncAttributeMaxDynamicSharedMemorySize, GEMM_SMEM);
    cudaFuncSetAttribute(attn_mma,
                         cudaFuncAttributeMaxDynamicSharedMemorySize, ATT_SMEM);

    // ---- prepass: tf32-round activations and weights once ----
    const int NA = MTOT * DMODEL;                 // 8388608
    const int NW = DMODEL * DMODEL;               // 1048576
    round_tf32_kernel<<<NA / 1024, 256>>>(query, aq, NA);
    round_tf32_kernel<<<NA / 1024, 256>>>(key_,  ak, NA);
    round_tf32_kernel<<<NA / 1024, 256>>>(value, av, NA);
    round_tf32_kernel<<<NW / 1024, 256>>>(Wq, wq, NW);
    round_tf32_kernel<<<NW / 1024, 256>>>(Wk, wk, NW);
    round_tf32_kernel<<<NW / 1024, 256>>>(Wv, wv, NW);
    round_tf32_kernel<<<NW / 1024, 256>>>(Wo, wo, NW);

    const int M = MTOT;                           // 8192
    dim3 ggrid(DMODEL / 128, M / 128);            // (8, 64)
    dim3 gblock(256);

    gemm_mma<<<ggrid, gblock, GEMM_SMEM>>>(aq, wq, bq, gq, 2);  // Q: tf32, *0.125*log2e
    gemm_mma<<<ggrid, gblock, GEMM_SMEM>>>(ak, wk, bk, gk, 0);  // K: tf32
    gemm_mma<<<ggrid, gblock, GEMM_SMEM>>>(av, wv, bv, gv, 0);  // V: tf32

    dim3 agrid(SEQ / 128, H_HEADS, BATCH);        // (16, 16, 4)
    attn_mma<<<agrid, dim3(128), ATT_SMEM>>>(gq, gk, gv, mask, gctx);

    gemm_mma<<<ggrid, gblock, GEMM_SMEM>>>(gctx, wo, bo, out, 1);
}